// round 3
// baseline (speedup 1.0000x reference)
#include <cuda_runtime.h>
#include <cuda_bf16.h>
#include <math.h>

// Problem constants
#define Bb   2
#define NN_  2048
#define CC   1024
#define HH   16
#define DD   64
#define DFF_ 4096

// Scratch buffers (static device globals — allocation-free rule)
__device__ float g_ln[Bb * NN_ * CC];
__device__ float g_qkv[Bb * NN_ * 3 * CC];
__device__ float g_attnout[Bb * NN_ * CC];
__device__ float g_x1[Bb * NN_ * CC];
__device__ float g_hbuf[Bb * NN_ * DFF_];

// ---------------------------------------------------------------------------
// LayerNorm: one block (256 threads) per row of C=1024
// ---------------------------------------------------------------------------
__global__ void ln_kernel(const float* __restrict__ x,
                          const float* __restrict__ g,
                          const float* __restrict__ b,
                          float* __restrict__ out)
{
    int row = blockIdx.x;
    long long base = (long long)row * CC;
    int t = threadIdx.x;

    float v[4];
    float s = 0.f, s2 = 0.f;
#pragma unroll
    for (int i = 0; i < 4; i++) {
        v[i] = x[base + t + i * 256];
        s  += v[i];
        s2 += v[i] * v[i];
    }
#pragma unroll
    for (int o = 16; o; o >>= 1) {
        s  += __shfl_xor_sync(0xffffffffu, s, o);
        s2 += __shfl_xor_sync(0xffffffffu, s2, o);
    }
    __shared__ float sh[16];
    int w = t >> 5, l = t & 31;
    if (l == 0) { sh[w] = s; sh[8 + w] = s2; }
    __syncthreads();
    if (t == 0) {
        float a = 0.f, c = 0.f;
#pragma unroll
        for (int i = 0; i < 8; i++) { a += sh[i]; c += sh[8 + i]; }
        sh[0] = a; sh[8] = c;
    }
    __syncthreads();
    float mu  = sh[0] * (1.0f / CC);
    float var = sh[8] * (1.0f / CC) - mu * mu;
    float inv = rsqrtf(var + 1e-5f);
#pragma unroll
    for (int i = 0; i < 4; i++) {
        int c = t + i * 256;
        out[base + c] = (v[i] - mu) * inv * g[c] + b[c];
    }
}

// ---------------------------------------------------------------------------
// Common device helpers
// ---------------------------------------------------------------------------
__device__ __forceinline__ float gelu_exact(float v) {
    return 0.5f * v * (1.0f + erff(v * 0.70710678118654752f));
}

__device__ __forceinline__ unsigned f2tf32(float f) {
    unsigned u;
    asm("cvt.rna.tf32.f32 %0, %1;" : "=r"(u) : "f"(f));
    return u;
}

__device__ __forceinline__ void mma_tf32(float* d, const unsigned* a, const unsigned* b) {
    asm volatile(
        "mma.sync.aligned.m16n8k8.row.col.f32.tf32.tf32.f32 "
        "{%0,%1,%2,%3}, {%4,%5,%6,%7}, {%8,%9}, {%0,%1,%2,%3};\n"
        : "+f"(d[0]), "+f"(d[1]), "+f"(d[2]), "+f"(d[3])
        : "r"(a[0]), "r"(a[1]), "r"(a[2]), "r"(a[3]),
          "r"(b[0]), "r"(b[1]));
}

// ---------------------------------------------------------------------------
// gemm_tc2: high-throughput NT TF32 GEMM (B is [Nc,K] row-major).
// CTA tile 128x256, BK=32, 8 warps (2 along M x 4 along N), warp tile 64x64.
// Double-buffered dynamic smem, register-staged global prefetch.
// All dims must divide tile sizes (they do here).
// ---------------------------------------------------------------------------
__global__ __launch_bounds__(256, 1)
void gemm_tc2(const float* __restrict__ A, const float* __restrict__ Bm,
              float* __restrict__ Cc,
              int M, int Nc, int K, int lda, int ldb, int ldc,
              long long Abs, long long Ahs,
              long long Bbs, long long Bhs,
              long long Cbs, long long Chs, int Hh,
              const float* __restrict__ bias,
              const float* __restrict__ res, int act)
{
    constexpr int BM = 128, BN = 256, BK = 32, LD = 36;
    constexpr int ABUF = BM * LD;          // words per A buffer
    constexpr int BUFW = (BM + BN) * LD;   // words per (A+B) stage
    extern __shared__ unsigned sm_[];

    int zb = blockIdx.z / Hh, zh = blockIdx.z % Hh;
    A  += zb * Abs + zh * Ahs;
    Bm += zb * Bbs + zh * Bhs;
    Cc += zb * Cbs + zh * Chs;

    int t = threadIdx.x, w = t >> 5, lane = t & 31;
    int gid = lane >> 2, tig = lane & 3;
    int m0 = blockIdx.y * BM, n0 = blockIdx.x * BN;
    int wm = (w & 1) * 64, wn = (w >> 1) * 64;

    int lrow = t >> 3;          // 0..31
    int lcol = (t & 7) * 4;     // 0..28

    float acc[4][8][4] = {};
    float4 ar[4], br[8];

    auto ldgA = [&](int k0) {
#pragma unroll
        for (int i = 0; i < 4; i++)
            ar[i] = *reinterpret_cast<const float4*>(
                &A[(long long)(m0 + lrow + 32 * i) * lda + k0 + lcol]);
    };
    auto ldgB = [&](int k0) {
#pragma unroll
        for (int i = 0; i < 8; i++)
            br[i] = *reinterpret_cast<const float4*>(
                &Bm[(long long)(n0 + lrow + 32 * i) * ldb + k0 + lcol]);
    };
    auto stsAB = [&](int buf) {
        unsigned* As = sm_ + buf * BUFW;
        unsigned* Bs = As + ABUF;
#pragma unroll
        for (int i = 0; i < 4; i++) {
            uint4 u = make_uint4(f2tf32(ar[i].x), f2tf32(ar[i].y),
                                 f2tf32(ar[i].z), f2tf32(ar[i].w));
            *reinterpret_cast<uint4*>(&As[(lrow + 32 * i) * LD + lcol]) = u;
        }
#pragma unroll
        for (int i = 0; i < 8; i++) {
            uint4 u = make_uint4(f2tf32(br[i].x), f2tf32(br[i].y),
                                 f2tf32(br[i].z), f2tf32(br[i].w));
            *reinterpret_cast<uint4*>(&Bs[(lrow + 32 * i) * LD + lcol]) = u;
        }
    };
    auto compute = [&](int buf, int kk0) {
        const unsigned* As = sm_ + buf * BUFW;
        const unsigned* Bs = As + ABUF;
#pragma unroll
        for (int s = 0; s < 2; s++) {
            int kk = kk0 + s * 8;
            unsigned af[4][4], bf[8][2];
#pragma unroll
            for (int i = 0; i < 4; i++) {
                int r = wm + i * 16 + gid;
                af[i][0] = As[r * LD + kk + tig];
                af[i][1] = As[(r + 8) * LD + kk + tig];
                af[i][2] = As[r * LD + kk + tig + 4];
                af[i][3] = As[(r + 8) * LD + kk + tig + 4];
            }
#pragma unroll
            for (int j = 0; j < 8; j++) {
                int c = wn + j * 8 + gid;
                bf[j][0] = Bs[c * LD + kk + tig];
                bf[j][1] = Bs[c * LD + kk + tig + 4];
            }
#pragma unroll
            for (int i = 0; i < 4; i++)
#pragma unroll
                for (int j = 0; j < 8; j++)
                    mma_tf32(acc[i][j], af[i], bf[j]);
        }
    };

    // pipeline
    ldgA(0); ldgB(0);
    stsAB(0);
    __syncthreads();
    int buf = 0;
    for (int k0 = 0; k0 < K; k0 += BK) {
        bool pf = (k0 + BK) < K;
        if (pf) ldgA(k0 + BK);
        compute(buf, 0);
        if (pf) ldgB(k0 + BK);
        compute(buf, 16);
        if (pf) {
            stsAB(buf ^ 1);
            __syncthreads();
        }
        buf ^= 1;
    }

    // epilogue
#pragma unroll
    for (int i = 0; i < 4; i++) {
        int r1 = m0 + wm + i * 16 + gid;
        int r2 = r1 + 8;
#pragma unroll
        for (int j = 0; j < 8; j++) {
            int c = n0 + wn + j * 8 + 2 * tig;
            float v0 = acc[i][j][0], v1 = acc[i][j][1];
            float v2 = acc[i][j][2], v3 = acc[i][j][3];
            if (bias) {
                float b0 = bias[c], b1 = bias[c + 1];
                v0 += b0; v1 += b1; v2 += b0; v3 += b1;
            }
            if (act) {
                v0 = gelu_exact(v0); v1 = gelu_exact(v1);
                v2 = gelu_exact(v2); v3 = gelu_exact(v3);
            }
            long long i1 = (long long)r1 * ldc + c;
            long long i2 = (long long)r2 * ldc + c;
            if (res) {
                float2 ra = *reinterpret_cast<const float2*>(&res[i1]);
                float2 rb = *reinterpret_cast<const float2*>(&res[i2]);
                v0 += ra.x; v1 += ra.y; v2 += rb.x; v3 += rb.y;
            }
            float2 o1 = {v0, v1}, o2 = {v2, v3};
            *reinterpret_cast<float2*>(&Cc[i1]) = o1;
            *reinterpret_cast<float2*>(&Cc[i2]) = o2;
        }
    }
}

// ---------------------------------------------------------------------------
// gemm_tc (from R2): used only for AV (B non-transposed, BN=64).
// ---------------------------------------------------------------------------
template <bool BT, int BM, int BN>
__global__ __launch_bounds__(256)
void gemm_tc(const float* __restrict__ A, const float* __restrict__ Bm,
             float* __restrict__ Cc,
             int M, int Nc, int K, int lda, int ldb, int ldc,
             long long Abs, long long Ahs,
             long long Bbs, long long Bhs,
             long long Cbs, long long Chs, int Hh,
             const float* __restrict__ bias,
             const float* __restrict__ res, int act)
{
    constexpr int BK = 32;
    constexpr int WM = BM / 4;
    constexpr int WN = BN / 2;
    constexpr int MT = WM / 16;
    constexpr int NT = WN / 8;
    constexpr int LDS_ = BK + 4;

    __shared__ unsigned As[BM][LDS_];
    __shared__ unsigned Bs[BN][LDS_];

    int zb = blockIdx.z / Hh, zh = blockIdx.z % Hh;
    A  += zb * Abs + zh * Ahs;
    Bm += zb * Bbs + zh * Bhs;
    Cc += zb * Cbs + zh * Chs;

    int t = threadIdx.x;
    int w = t >> 5, lane = t & 31;
    int gid = lane >> 2, tig = lane & 3;
    int m0 = blockIdx.y * BM, n0 = blockIdx.x * BN;
    int wm = (w & 3) * WM, wn = (w >> 2) * WN;

    float acc[MT][NT][4] = {};

    int la_col = (t & 7) * 4;
    int la_row = t >> 3;
    int lb_nc  = (t & 15) * 4;
    int lb_kr  = t >> 4;

    for (int k0 = 0; k0 < K; k0 += BK) {
#pragma unroll
        for (int r = la_row; r < BM; r += 32) {
            float4 v = *reinterpret_cast<const float4*>(
                &A[(long long)(m0 + r) * lda + k0 + la_col]);
            As[r][la_col + 0] = f2tf32(v.x);
            As[r][la_col + 1] = f2tf32(v.y);
            As[r][la_col + 2] = f2tf32(v.z);
            As[r][la_col + 3] = f2tf32(v.w);
        }
        if (BT) {
#pragma unroll
            for (int r = la_row; r < BN; r += 32) {
                float4 v = *reinterpret_cast<const float4*>(
                    &Bm[(long long)(n0 + r) * ldb + k0 + la_col]);
                Bs[r][la_col + 0] = f2tf32(v.x);
                Bs[r][la_col + 1] = f2tf32(v.y);
                Bs[r][la_col + 2] = f2tf32(v.z);
                Bs[r][la_col + 3] = f2tf32(v.w);
            }
        } else {
#pragma unroll
            for (int k2 = lb_kr; k2 < BK; k2 += 16) {
                float4 v = *reinterpret_cast<const float4*>(
                    &Bm[(long long)(k0 + k2) * ldb + n0 + lb_nc]);
                Bs[lb_nc + 0][k2] = f2tf32(v.x);
                Bs[lb_nc + 1][k2] = f2tf32(v.y);
                Bs[lb_nc + 2][k2] = f2tf32(v.z);
                Bs[lb_nc + 3][k2] = f2tf32(v.w);
            }
        }
        __syncthreads();

#pragma unroll
        for (int kk = 0; kk < BK; kk += 8) {
            unsigned af[MT][4], bf[NT][2];
#pragma unroll
            for (int i = 0; i < MT; i++) {
                int r = wm + i * 16 + gid;
                af[i][0] = As[r][kk + tig];
                af[i][1] = As[r + 8][kk + tig];
                af[i][2] = As[r][kk + tig + 4];
                af[i][3] = As[r + 8][kk + tig + 4];
            }
#pragma unroll
            for (int j = 0; j < NT; j++) {
                int c = wn + j * 8 + gid;
                bf[j][0] = Bs[c][kk + tig];
                bf[j][1] = Bs[c][kk + tig + 4];
            }
#pragma unroll
            for (int i = 0; i < MT; i++)
#pragma unroll
                for (int j = 0; j < NT; j++)
                    mma_tf32(acc[i][j], af[i], bf[j]);
        }
        __syncthreads();
    }

#pragma unroll
    for (int i = 0; i < MT; i++) {
        int r1 = m0 + wm + i * 16 + gid;
        int r2 = r1 + 8;
#pragma unroll
        for (int j = 0; j < NT; j++) {
            int c = n0 + wn + j * 8 + 2 * tig;
            float v0 = acc[i][j][0], v1 = acc[i][j][1];
            float v2 = acc[i][j][2], v3 = acc[i][j][3];
            if (bias) {
                float b0 = bias[c], b1 = bias[c + 1];
                v0 += b0; v1 += b1; v2 += b0; v3 += b1;
            }
            if (act) {
                v0 = gelu_exact(v0); v1 = gelu_exact(v1);
                v2 = gelu_exact(v2); v3 = gelu_exact(v3);
            }
            long long i1 = (long long)r1 * ldc + c;
            long long i2 = (long long)r2 * ldc + c;
            if (res) {
                float2 ra = *reinterpret_cast<const float2*>(&res[i1]);
                float2 rb = *reinterpret_cast<const float2*>(&res[i2]);
                v0 += ra.x; v1 += ra.y; v2 += rb.x; v3 += rb.y;
            }
            float2 o1 = {v0, v1}, o2 = {v2, v3};
            *reinterpret_cast<float2*>(&Cc[i1]) = o1;
            *reinterpret_cast<float2*>(&Cc[i2]) = o2;
        }
    }
}

// ---------------------------------------------------------------------------
// Softmax (in place): scale + mask + softmax, row length N=2048.
// ---------------------------------------------------------------------------
__global__ void softmax_kernel(float* __restrict__ attn,
                               const int* __restrict__ mask)
{
    long long row = blockIdx.x;
    int bidx = (int)(row / ((long long)HH * NN_));
    float* r = attn + row * NN_;
    const int* mr = mask + (long long)bidx * NN_;
    int t = threadIdx.x;

    const float scale = 0.125f;

    float v[8];
    float mx = -INFINITY;
#pragma unroll
    for (int i = 0; i < 8; i++) {
        int c = t + i * 256;
        float val = mr[c] ? r[c] * scale : -INFINITY;
        v[i] = val;
        mx = fmaxf(mx, val);
    }
#pragma unroll
    for (int o = 16; o; o >>= 1)
        mx = fmaxf(mx, __shfl_xor_sync(0xffffffffu, mx, o));

    __shared__ float shm[8], shs[8];
    int w = t >> 5, l = t & 31;
    if (l == 0) shm[w] = mx;
    __syncthreads();
    float m2 = shm[0];
#pragma unroll
    for (int i = 1; i < 8; i++) m2 = fmaxf(m2, shm[i]);

    float se = 0.f;
#pragma unroll
    for (int i = 0; i < 8; i++) {
        v[i] = expf(v[i] - m2);
        se += v[i];
    }
#pragma unroll
    for (int o = 16; o; o >>= 1)
        se += __shfl_xor_sync(0xffffffffu, se, o);
    if (l == 0) shs[w] = se;
    __syncthreads();
    float tot = 0.f;
#pragma unroll
    for (int i = 0; i < 8; i++) tot += shs[i];
    float inv = 1.0f / tot;

#pragma unroll
    for (int i = 0; i < 8; i++) {
        int c = t + i * 256;
        r[c] = v[i] * inv;
    }
}

// ---------------------------------------------------------------------------
// Launch
// ---------------------------------------------------------------------------
extern "C" void kernel_launch(void* const* d_in, const int* in_sizes, int n_in,
                              void* d_out, int out_size)
{
    const float* x      = (const float*)d_in[0];
    const int*   mask   = (const int*)  d_in[1];
    const float* qkv_w  = (const float*)d_in[2];
    const float* proj_w = (const float*)d_in[3];
    const float* proj_b = (const float*)d_in[4];
    const float* ln1_g  = (const float*)d_in[5];
    const float* ln1_b  = (const float*)d_in[6];
    const float* ln2_g  = (const float*)d_in[7];
    const float* ln2_b  = (const float*)d_in[8];
    const float* fc1_w  = (const float*)d_in[9];
    const float* fc1_b  = (const float*)d_in[10];
    const float* fc2_w  = (const float*)d_in[11];
    const float* fc2_b  = (const float*)d_in[12];

    float* out_x    = (float*)d_out;
    float* out_attn = out_x + (long long)Bb * NN_ * CC;

    float *p_ln, *p_qkv, *p_ao, *p_x1, *p_h;
    cudaGetSymbolAddress((void**)&p_ln,  g_ln);
    cudaGetSymbolAddress((void**)&p_qkv, g_qkv);
    cudaGetSymbolAddress((void**)&p_ao,  g_attnout);
    cudaGetSymbolAddress((void**)&p_x1,  g_x1);
    cudaGetSymbolAddress((void**)&p_h,   g_hbuf);

    const int M  = Bb * NN_;                 // 4096
    const long long ZERO = 0;
    const long long NC3 = (long long)NN_ * 3 * CC;
    const int SMEM2 = (128 + 256) * 36 * 4 * 2;   // 110592 bytes

    cudaFuncSetAttribute(gemm_tc2, cudaFuncAttributeMaxDynamicSharedMemorySize, SMEM2);

    // 1) LN1
    ln_kernel<<<M, 256>>>(x, ln1_g, ln1_b, p_ln);

    // 2) QKV: [4096,3072] = ln @ qkv_w^T
    {
        dim3 grid(3 * CC / 256, M / 128, 1);
        gemm_tc2<<<grid, 256, SMEM2>>>(p_ln, qkv_w, p_qkv,
            M, 3 * CC, CC, CC, CC, 3 * CC,
            ZERO, ZERO, ZERO, ZERO, ZERO, ZERO, 1,
            nullptr, nullptr, 0);
    }

    // 3) QK^T per head -> out_attn (raw logits)
    {
        dim3 grid(NN_ / 256, NN_ / 128, Bb * HH);
        gemm_tc2<<<grid, 256, SMEM2>>>(p_qkv, p_qkv + CC, out_attn,
            NN_, NN_, DD, 3 * CC, 3 * CC, NN_,
            NC3, DD, NC3, DD,
            (long long)HH * NN_ * NN_, (long long)NN_ * NN_, HH,
            nullptr, nullptr, 0);
    }

    // 4) softmax (scale + mask), in place
    softmax_kernel<<<Bb * HH * NN_, 256>>>(out_attn, mask);

    // 5) AV per head: [2048,64] = attn @ V
    {
        dim3 grid(1, NN_ / 128, Bb * HH);
        gemm_tc<false, 128, 64><<<grid, 256>>>(out_attn, p_qkv + 2 * CC, p_ao,
            NN_, DD, NN_, NN_, 3 * CC, CC,
            (long long)HH * NN_ * NN_, (long long)NN_ * NN_,
            NC3, DD,
            (long long)NN_ * CC, DD, HH,
            nullptr, nullptr, 0);
    }

    // 6) proj + residual: x1 = x + ao @ proj_w^T + proj_b
    {
        dim3 grid(CC / 256, M / 128, 1);
        gemm_tc2<<<grid, 256, SMEM2>>>(p_ao, proj_w, p_x1,
            M, CC, CC, CC, CC, CC,
            ZERO, ZERO, ZERO, ZERO, ZERO, ZERO, 1,
            proj_b, x, 0);
    }

    // 7) LN2
    ln_kernel<<<M, 256>>>(p_x1, ln2_g, ln2_b, p_ln);

    // 8) FC1 + GELU
    {
        dim3 grid(DFF_ / 256, M / 128, 1);
        gemm_tc2<<<grid, 256, SMEM2>>>(p_ln, fc1_w, p_h,
            M, DFF_, CC, CC, CC, DFF_,
            ZERO, ZERO, ZERO, ZERO, ZERO, ZERO, 1,
            fc1_b, nullptr, 1);
    }

    // 9) FC2 + residual
    {
        dim3 grid(CC / 256, M / 128, 1);
        gemm_tc2<<<grid, 256, SMEM2>>>(p_h, fc2_w, out_x,
            M, CC, DFF_, DFF_, DFF_, CC,
            ZERO, ZERO, ZERO, ZERO, ZERO, ZERO, 1,
            fc2_b, p_x1, 0);
    }
}

// round 4
// speedup vs baseline: 1.2914x; 1.2914x over previous
#include <cuda_runtime.h>
#include <cuda_bf16.h>
#include <math.h>

// Problem constants
#define Bb   2
#define NN_  2048
#define CC   1024
#define HH   16
#define DD   64
#define DFF_ 4096

// Scratch buffers (static device globals — allocation-free rule)
__device__ float g_ln[Bb * NN_ * CC];
__device__ float g_qkv[Bb * NN_ * 3 * CC];
__device__ float g_attnout[Bb * NN_ * CC];
__device__ float g_x1[Bb * NN_ * CC];
__device__ float g_hbuf[Bb * NN_ * DFF_];

// ---------------------------------------------------------------------------
// LayerNorm: one block (256 threads) per row of C=1024
// ---------------------------------------------------------------------------
__global__ void ln_kernel(const float* __restrict__ x,
                          const float* __restrict__ g,
                          const float* __restrict__ b,
                          float* __restrict__ out)
{
    int row = blockIdx.x;
    long long base = (long long)row * CC;
    int t = threadIdx.x;

    float v[4];
    float s = 0.f, s2 = 0.f;
#pragma unroll
    for (int i = 0; i < 4; i++) {
        v[i] = x[base + t + i * 256];
        s  += v[i];
        s2 += v[i] * v[i];
    }
#pragma unroll
    for (int o = 16; o; o >>= 1) {
        s  += __shfl_xor_sync(0xffffffffu, s, o);
        s2 += __shfl_xor_sync(0xffffffffu, s2, o);
    }
    __shared__ float sh[16];
    int w = t >> 5, l = t & 31;
    if (l == 0) { sh[w] = s; sh[8 + w] = s2; }
    __syncthreads();
    if (t == 0) {
        float a = 0.f, c = 0.f;
#pragma unroll
        for (int i = 0; i < 8; i++) { a += sh[i]; c += sh[8 + i]; }
        sh[0] = a; sh[8] = c;
    }
    __syncthreads();
    float mu  = sh[0] * (1.0f / CC);
    float var = sh[8] * (1.0f / CC) - mu * mu;
    float inv = rsqrtf(var + 1e-5f);
#pragma unroll
    for (int i = 0; i < 4; i++) {
        int c = t + i * 256;
        out[base + c] = (v[i] - mu) * inv * g[c] + b[c];
    }
}

// ---------------------------------------------------------------------------
// Common device helpers
// ---------------------------------------------------------------------------
__device__ __forceinline__ float gelu_exact(float v) {
    return 0.5f * v * (1.0f + erff(v * 0.70710678118654752f));
}

__device__ __forceinline__ unsigned f2tf32(float f) {
    unsigned u;
    asm("cvt.rna.tf32.f32 %0, %1;" : "=r"(u) : "f"(f));
    return u;
}

__device__ __forceinline__ void mma_tf32(float* d, const unsigned* a, const unsigned* b) {
    asm volatile(
        "mma.sync.aligned.m16n8k8.row.col.f32.tf32.tf32.f32 "
        "{%0,%1,%2,%3}, {%4,%5,%6,%7}, {%8,%9}, {%0,%1,%2,%3};\n"
        : "+f"(d[0]), "+f"(d[1]), "+f"(d[2]), "+f"(d[3])
        : "r"(a[0]), "r"(a[1]), "r"(a[2]), "r"(a[3]),
          "r"(b[0]), "r"(b[1]));
}

// ---------------------------------------------------------------------------
// gemm_tc3: double-buffered NT TF32 GEMM (B is [Nc,K] row-major).
// CTA tile 128x128, BK=32, 8 warps (2 along M x 4 along N), warp tile 64x32.
// Register-staged global prefetch, one __syncthreads per BK iteration.
// All dims must divide tile sizes (true for this problem).
// ---------------------------------------------------------------------------
__global__ __launch_bounds__(256)
void gemm_tc3(const float* __restrict__ A, const float* __restrict__ Bm,
              float* __restrict__ Cc,
              int M, int Nc, int K, int lda, int ldb, int ldc,
              long long Abs, long long Ahs,
              long long Bbs, long long Bhs,
              long long Cbs, long long Chs, int Hh,
              const float* __restrict__ bias,
              const float* __restrict__ res, int act)
{
    constexpr int BM = 128, BN = 128, BK = 32, LD = 36;
    constexpr int ABUF = BM * LD;
    constexpr int BUFW = (BM + BN) * LD;
    extern __shared__ unsigned sm_[];

    int zb = blockIdx.z / Hh, zh = blockIdx.z % Hh;
    A  += zb * Abs + zh * Ahs;
    Bm += zb * Bbs + zh * Bhs;
    Cc += zb * Cbs + zh * Chs;

    int t = threadIdx.x, w = t >> 5, lane = t & 31;
    int gid = lane >> 2, tig = lane & 3;
    int m0 = blockIdx.y * BM, n0 = blockIdx.x * BN;
    int wm = (w & 1) * 64;      // 2 warps along M, tile 64
    int wn = (w >> 1) * 32;     // 4 warps along N, tile 32

    int lrow = t >> 3;          // 0..31
    int lcol = (t & 7) * 4;     // 0..28

    float acc[4][4][4] = {};    // MT=4 (m16), NT=4 (n8)
    float4 ar[4], br[4];

    auto ldgA = [&](int k0) {
#pragma unroll
        for (int i = 0; i < 4; i++)
            ar[i] = *reinterpret_cast<const float4*>(
                &A[(long long)(m0 + lrow + 32 * i) * lda + k0 + lcol]);
    };
    auto ldgB = [&](int k0) {
#pragma unroll
        for (int i = 0; i < 4; i++)
            br[i] = *reinterpret_cast<const float4*>(
                &Bm[(long long)(n0 + lrow + 32 * i) * ldb + k0 + lcol]);
    };
    auto stsAB = [&](int buf) {
        unsigned* As = sm_ + buf * BUFW;
        unsigned* Bs = As + ABUF;
#pragma unroll
        for (int i = 0; i < 4; i++) {
            uint4 u = make_uint4(f2tf32(ar[i].x), f2tf32(ar[i].y),
                                 f2tf32(ar[i].z), f2tf32(ar[i].w));
            *reinterpret_cast<uint4*>(&As[(lrow + 32 * i) * LD + lcol]) = u;
        }
#pragma unroll
        for (int i = 0; i < 4; i++) {
            uint4 u = make_uint4(f2tf32(br[i].x), f2tf32(br[i].y),
                                 f2tf32(br[i].z), f2tf32(br[i].w));
            *reinterpret_cast<uint4*>(&Bs[(lrow + 32 * i) * LD + lcol]) = u;
        }
    };
    auto compute = [&](int buf, int kk0) {
        const unsigned* As = sm_ + buf * BUFW;
        const unsigned* Bs = As + ABUF;
#pragma unroll
        for (int s = 0; s < 2; s++) {
            int kk = kk0 + s * 8;
            unsigned af[4][4], bf[4][2];
#pragma unroll
            for (int i = 0; i < 4; i++) {
                int r = wm + i * 16 + gid;
                af[i][0] = As[r * LD + kk + tig];
                af[i][1] = As[(r + 8) * LD + kk + tig];
                af[i][2] = As[r * LD + kk + tig + 4];
                af[i][3] = As[(r + 8) * LD + kk + tig + 4];
            }
#pragma unroll
            for (int j = 0; j < 4; j++) {
                int c = wn + j * 8 + gid;
                bf[j][0] = Bs[c * LD + kk + tig];
                bf[j][1] = Bs[c * LD + kk + tig + 4];
            }
#pragma unroll
            for (int i = 0; i < 4; i++)
#pragma unroll
                for (int j = 0; j < 4; j++)
                    mma_tf32(acc[i][j], af[i], bf[j]);
        }
    };

    // pipeline
    ldgA(0); ldgB(0);
    stsAB(0);
    __syncthreads();
    int buf = 0;
    for (int k0 = 0; k0 < K; k0 += BK) {
        bool pf = (k0 + BK) < K;
        if (pf) ldgA(k0 + BK);
        compute(buf, 0);
        if (pf) ldgB(k0 + BK);
        compute(buf, 16);
        if (pf) {
            stsAB(buf ^ 1);
            __syncthreads();
        }
        buf ^= 1;
    }

    // epilogue
#pragma unroll
    for (int i = 0; i < 4; i++) {
        int r1 = m0 + wm + i * 16 + gid;
        int r2 = r1 + 8;
#pragma unroll
        for (int j = 0; j < 4; j++) {
            int c = n0 + wn + j * 8 + 2 * tig;
            float v0 = acc[i][j][0], v1 = acc[i][j][1];
            float v2 = acc[i][j][2], v3 = acc[i][j][3];
            if (bias) {
                float b0 = bias[c], b1 = bias[c + 1];
                v0 += b0; v1 += b1; v2 += b0; v3 += b1;
            }
            if (act) {
                v0 = gelu_exact(v0); v1 = gelu_exact(v1);
                v2 = gelu_exact(v2); v3 = gelu_exact(v3);
            }
            long long i1 = (long long)r1 * ldc + c;
            long long i2 = (long long)r2 * ldc + c;
            if (res) {
                float2 ra = *reinterpret_cast<const float2*>(&res[i1]);
                float2 rb = *reinterpret_cast<const float2*>(&res[i2]);
                v0 += ra.x; v1 += ra.y; v2 += rb.x; v3 += rb.y;
            }
            float2 o1 = {v0, v1}, o2 = {v2, v3};
            *reinterpret_cast<float2*>(&Cc[i1]) = o1;
            *reinterpret_cast<float2*>(&Cc[i2]) = o2;
        }
    }
}

// ---------------------------------------------------------------------------
// gemm_tc (from R2): used only for AV (B non-transposed, BN=64).
// ---------------------------------------------------------------------------
template <bool BT, int BM, int BN>
__global__ __launch_bounds__(256)
void gemm_tc(const float* __restrict__ A, const float* __restrict__ Bm,
             float* __restrict__ Cc,
             int M, int Nc, int K, int lda, int ldb, int ldc,
             long long Abs, long long Ahs,
             long long Bbs, long long Bhs,
             long long Cbs, long long Chs, int Hh,
             const float* __restrict__ bias,
             const float* __restrict__ res, int act)
{
    constexpr int BK = 32;
    constexpr int WM = BM / 4;
    constexpr int WN = BN / 2;
    constexpr int MT = WM / 16;
    constexpr int NT = WN / 8;
    constexpr int LDS_ = BK + 4;

    __shared__ unsigned As[BM][LDS_];
    __shared__ unsigned Bs[BN][LDS_];

    int zb = blockIdx.z / Hh, zh = blockIdx.z % Hh;
    A  += zb * Abs + zh * Ahs;
    Bm += zb * Bbs + zh * Bhs;
    Cc += zb * Cbs + zh * Chs;

    int t = threadIdx.x;
    int w = t >> 5, lane = t & 31;
    int gid = lane >> 2, tig = lane & 3;
    int m0 = blockIdx.y * BM, n0 = blockIdx.x * BN;
    int wm = (w & 3) * WM, wn = (w >> 2) * WN;

    float acc[MT][NT][4] = {};

    int la_col = (t & 7) * 4;
    int la_row = t >> 3;
    int lb_nc  = (t & 15) * 4;
    int lb_kr  = t >> 4;

    for (int k0 = 0; k0 < K; k0 += BK) {
#pragma unroll
        for (int r = la_row; r < BM; r += 32) {
            float4 v = *reinterpret_cast<const float4*>(
                &A[(long long)(m0 + r) * lda + k0 + la_col]);
            As[r][la_col + 0] = f2tf32(v.x);
            As[r][la_col + 1] = f2tf32(v.y);
            As[r][la_col + 2] = f2tf32(v.z);
            As[r][la_col + 3] = f2tf32(v.w);
        }
        if (BT) {
#pragma unroll
            for (int r = la_row; r < BN; r += 32) {
                float4 v = *reinterpret_cast<const float4*>(
                    &Bm[(long long)(n0 + r) * ldb + k0 + la_col]);
                Bs[r][la_col + 0] = f2tf32(v.x);
                Bs[r][la_col + 1] = f2tf32(v.y);
                Bs[r][la_col + 2] = f2tf32(v.z);
                Bs[r][la_col + 3] = f2tf32(v.w);
            }
        } else {
#pragma unroll
            for (int k2 = lb_kr; k2 < BK; k2 += 16) {
                float4 v = *reinterpret_cast<const float4*>(
                    &Bm[(long long)(k0 + k2) * ldb + n0 + lb_nc]);
                Bs[lb_nc + 0][k2] = f2tf32(v.x);
                Bs[lb_nc + 1][k2] = f2tf32(v.y);
                Bs[lb_nc + 2][k2] = f2tf32(v.z);
                Bs[lb_nc + 3][k2] = f2tf32(v.w);
            }
        }
        __syncthreads();

#pragma unroll
        for (int kk = 0; kk < BK; kk += 8) {
            unsigned af[MT][4], bf[NT][2];
#pragma unroll
            for (int i = 0; i < MT; i++) {
                int r = wm + i * 16 + gid;
                af[i][0] = As[r][kk + tig];
                af[i][1] = As[r + 8][kk + tig];
                af[i][2] = As[r][kk + tig + 4];
                af[i][3] = As[r + 8][kk + tig + 4];
            }
#pragma unroll
            for (int j = 0; j < NT; j++) {
                int c = wn + j * 8 + gid;
                bf[j][0] = Bs[c][kk + tig];
                bf[j][1] = Bs[c][kk + tig + 4];
            }
#pragma unroll
            for (int i = 0; i < MT; i++)
#pragma unroll
                for (int j = 0; j < NT; j++)
                    mma_tf32(acc[i][j], af[i], bf[j]);
        }
        __syncthreads();
    }

#pragma unroll
    for (int i = 0; i < MT; i++) {
        int r1 = m0 + wm + i * 16 + gid;
        int r2 = r1 + 8;
#pragma unroll
        for (int j = 0; j < NT; j++) {
            int c = n0 + wn + j * 8 + 2 * tig;
            float v0 = acc[i][j][0], v1 = acc[i][j][1];
            float v2 = acc[i][j][2], v3 = acc[i][j][3];
            if (bias) {
                float b0 = bias[c], b1 = bias[c + 1];
                v0 += b0; v1 += b1; v2 += b0; v3 += b1;
            }
            if (act) {
                v0 = gelu_exact(v0); v1 = gelu_exact(v1);
                v2 = gelu_exact(v2); v3 = gelu_exact(v3);
            }
            long long i1 = (long long)r1 * ldc + c;
            long long i2 = (long long)r2 * ldc + c;
            if (res) {
                float2 ra = *reinterpret_cast<const float2*>(&res[i1]);
                float2 rb = *reinterpret_cast<const float2*>(&res[i2]);
                v0 += ra.x; v1 += ra.y; v2 += rb.x; v3 += rb.y;
            }
            float2 o1 = {v0, v1}, o2 = {v2, v3};
            *reinterpret_cast<float2*>(&Cc[i1]) = o1;
            *reinterpret_cast<float2*>(&Cc[i2]) = o2;
        }
    }
}

// ---------------------------------------------------------------------------
// Softmax (in place): scale + mask + softmax, row length N=2048.
// ---------------------------------------------------------------------------
__global__ void softmax_kernel(float* __restrict__ attn,
                               const int* __restrict__ mask)
{
    long long row = blockIdx.x;
    int bidx = (int)(row / ((long long)HH * NN_));
    float* r = attn + row * NN_;
    const int* mr = mask + (long long)bidx * NN_;
    int t = threadIdx.x;

    const float scale = 0.125f;

    float v[8];
    float mx = -INFINITY;
#pragma unroll
    for (int i = 0; i < 8; i++) {
        int c = t + i * 256;
        float val = mr[c] ? r[c] * scale : -INFINITY;
        v[i] = val;
        mx = fmaxf(mx, val);
    }
#pragma unroll
    for (int o = 16; o; o >>= 1)
        mx = fmaxf(mx, __shfl_xor_sync(0xffffffffu, mx, o));

    __shared__ float shm[8], shs[8];
    int w = t >> 5, l = t & 31;
    if (l == 0) shm[w] = mx;
    __syncthreads();
    float m2 = shm[0];
#pragma unroll
    for (int i = 1; i < 8; i++) m2 = fmaxf(m2, shm[i]);

    float se = 0.f;
#pragma unroll
    for (int i = 0; i < 8; i++) {
        v[i] = expf(v[i] - m2);
        se += v[i];
    }
#pragma unroll
    for (int o = 16; o; o >>= 1)
        se += __shfl_xor_sync(0xffffffffu, se, o);
    if (l == 0) shs[w] = se;
    __syncthreads();
    float tot = 0.f;
#pragma unroll
    for (int i = 0; i < 8; i++) tot += shs[i];
    float inv = 1.0f / tot;

#pragma unroll
    for (int i = 0; i < 8; i++) {
        int c = t + i * 256;
        r[c] = v[i] * inv;
    }
}

// ---------------------------------------------------------------------------
// Launch
// ---------------------------------------------------------------------------
extern "C" void kernel_launch(void* const* d_in, const int* in_sizes, int n_in,
                              void* d_out, int out_size)
{
    const float* x      = (const float*)d_in[0];
    const int*   mask   = (const int*)  d_in[1];
    const float* qkv_w  = (const float*)d_in[2];
    const float* proj_w = (const float*)d_in[3];
    const float* proj_b = (const float*)d_in[4];
    const float* ln1_g  = (const float*)d_in[5];
    const float* ln1_b  = (const float*)d_in[6];
    const float* ln2_g  = (const float*)d_in[7];
    const float* ln2_b  = (const float*)d_in[8];
    const float* fc1_w  = (const float*)d_in[9];
    const float* fc1_b  = (const float*)d_in[10];
    const float* fc2_w  = (const float*)d_in[11];
    const float* fc2_b  = (const float*)d_in[12];

    float* out_x    = (float*)d_out;
    float* out_attn = out_x + (long long)Bb * NN_ * CC;

    float *p_ln, *p_qkv, *p_ao, *p_x1, *p_h;
    cudaGetSymbolAddress((void**)&p_ln,  g_ln);
    cudaGetSymbolAddress((void**)&p_qkv, g_qkv);
    cudaGetSymbolAddress((void**)&p_ao,  g_attnout);
    cudaGetSymbolAddress((void**)&p_x1,  g_x1);
    cudaGetSymbolAddress((void**)&p_h,   g_hbuf);

    const int M  = Bb * NN_;                 // 4096
    const long long ZERO = 0;
    const long long NC3 = (long long)NN_ * 3 * CC;
    const int SMEM3 = (128 + 128) * 36 * 4 * 2;   // 73728 bytes

    cudaFuncSetAttribute(gemm_tc3, cudaFuncAttributeMaxDynamicSharedMemorySize, SMEM3);

    // 1) LN1
    ln_kernel<<<M, 256>>>(x, ln1_g, ln1_b, p_ln);

    // 2) QKV: [4096,3072] = ln @ qkv_w^T
    {
        dim3 grid(3 * CC / 128, M / 128, 1);
        gemm_tc3<<<grid, 256, SMEM3>>>(p_ln, qkv_w, p_qkv,
            M, 3 * CC, CC, CC, CC, 3 * CC,
            ZERO, ZERO, ZERO, ZERO, ZERO, ZERO, 1,
            nullptr, nullptr, 0);
    }

    // 3) QK^T per head -> out_attn (raw logits)
    {
        dim3 grid(NN_ / 128, NN_ / 128, Bb * HH);
        gemm_tc3<<<grid, 256, SMEM3>>>(p_qkv, p_qkv + CC, out_attn,
            NN_, NN_, DD, 3 * CC, 3 * CC, NN_,
            NC3, DD, NC3, DD,
            (long long)HH * NN_ * NN_, (long long)NN_ * NN_, HH,
            nullptr, nullptr, 0);
    }

    // 4) softmax (scale + mask), in place
    softmax_kernel<<<Bb * HH * NN_, 256>>>(out_attn, mask);

    // 5) AV per head: [2048,64] = attn @ V
    {
        dim3 grid(1, NN_ / 128, Bb * HH);
        gemm_tc<false, 128, 64><<<grid, 256>>>(out_attn, p_qkv + 2 * CC, p_ao,
            NN_, DD, NN_, NN_, 3 * CC, CC,
            (long long)HH * NN_ * NN_, (long long)NN_ * NN_,
            NC3, DD,
            (long long)NN_ * CC, DD, HH,
            nullptr, nullptr, 0);
    }

    // 6) proj + residual: x1 = x + ao @ proj_w^T + proj_b
    {
        dim3 grid(CC / 128, M / 128, 1);
        gemm_tc3<<<grid, 256, SMEM3>>>(p_ao, proj_w, p_x1,
            M, CC, CC, CC, CC, CC,
            ZERO, ZERO, ZERO, ZERO, ZERO, ZERO, 1,
            proj_b, x, 0);
    }

    // 7) LN2
    ln_kernel<<<M, 256>>>(p_x1, ln2_g, ln2_b, p_ln);

    // 8) FC1 + GELU
    {
        dim3 grid(DFF_ / 128, M / 128, 1);
        gemm_tc3<<<grid, 256, SMEM3>>>(p_ln, fc1_w, p_h,
            M, DFF_, CC, CC, CC, DFF_,
            ZERO, ZERO, ZERO, ZERO, ZERO, ZERO, 1,
            fc1_b, nullptr, 1);
    }

    // 9) FC2 + residual
    {
        dim3 grid(CC / 128, M / 128, 1);
        gemm_tc3<<<grid, 256, SMEM3>>>(p_h, fc2_w, out_x,
            M, CC, DFF_, DFF_, DFF_, CC,
            ZERO, ZERO, ZERO, ZERO, ZERO, ZERO, 1,
            fc2_b, p_x1, 0);
    }
}

// round 6
// speedup vs baseline: 1.3580x; 1.0516x over previous
#include <cuda_runtime.h>
#include <cuda_bf16.h>
#include <math.h>
#include <stdint.h>

// Problem constants
#define Bb   2
#define NN_  2048
#define CC   1024
#define HH   16
#define DD   64
#define DFF_ 4096

// Scratch buffers (static device globals — allocation-free rule)
__device__ float g_ln[Bb * NN_ * CC];
__device__ float g_qkv[Bb * NN_ * 3 * CC];
__device__ float g_attnout[Bb * NN_ * CC];
__device__ float g_x1[Bb * NN_ * CC];
__device__ float g_hbuf[Bb * NN_ * DFF_];
// tf32-rounded weight copies
__device__ float g_wq[3 * CC * CC];
__device__ float g_wp[CC * CC];
__device__ float g_w1[DFF_ * CC];
__device__ float g_w2[CC * DFF_];

// ---------------------------------------------------------------------------
// helpers
// ---------------------------------------------------------------------------
__device__ __forceinline__ unsigned f2tf32(float f) {
    unsigned u;
    asm("cvt.rna.tf32.f32 %0, %1;" : "=r"(u) : "f"(f));
    return u;
}
__device__ __forceinline__ float rnd_tf32(float f) {
    return __uint_as_float(f2tf32(f));
}
__device__ __forceinline__ float gelu_exact(float v) {
    return 0.5f * v * (1.0f + erff(v * 0.70710678118654752f));
}
__device__ __forceinline__ uint32_t smem_u32(const void* p) {
    uint32_t a;
    asm("{ .reg .u64 t; cvta.to.shared.u64 t, %1; cvt.u32.u64 %0, t; }"
        : "=r"(a) : "l"(p));
    return a;
}
__device__ __forceinline__ void cp16(uint32_t dst, const void* src) {
    asm volatile("cp.async.cg.shared.global [%0], [%1], 16;"
                 :: "r"(dst), "l"(src) : "memory");
}
__device__ __forceinline__ void mma_tf32(float* d, const unsigned* a, const unsigned* b) {
    asm volatile(
        "mma.sync.aligned.m16n8k8.row.col.f32.tf32.tf32.f32 "
        "{%0,%1,%2,%3}, {%4,%5,%6,%7}, {%8,%9}, {%0,%1,%2,%3};\n"
        : "+f"(d[0]), "+f"(d[1]), "+f"(d[2]), "+f"(d[3])
        : "r"(a[0]), "r"(a[1]), "r"(a[2]), "r"(a[3]),
          "r"(b[0]), "r"(b[1]));
}

// ---------------------------------------------------------------------------
// weight pre-round: d = round_tf32(s)
// ---------------------------------------------------------------------------
__global__ void rnd_kernel(const float* __restrict__ s, float* __restrict__ d, int n)
{
    int i = (blockIdx.x * 256 + threadIdx.x) * 4;
    if (i < n) {
        float4 v = *reinterpret_cast<const float4*>(&s[i]);
        v.x = rnd_tf32(v.x); v.y = rnd_tf32(v.y);
        v.z = rnd_tf32(v.z); v.w = rnd_tf32(v.w);
        *reinterpret_cast<float4*>(&d[i]) = v;
    }
}

// ---------------------------------------------------------------------------
// LayerNorm (output rounded to tf32 — it only feeds GEMMs)
// ---------------------------------------------------------------------------
__global__ void ln_kernel(const float* __restrict__ x,
                          const float* __restrict__ g,
                          const float* __restrict__ b,
                          float* __restrict__ out)
{
    int row = blockIdx.x;
    long long base = (long long)row * CC;
    int t = threadIdx.x;

    float v[4];
    float s = 0.f, s2 = 0.f;
#pragma unroll
    for (int i = 0; i < 4; i++) {
        v[i] = x[base + t + i * 256];
        s  += v[i];
        s2 += v[i] * v[i];
    }
#pragma unroll
    for (int o = 16; o; o >>= 1) {
        s  += __shfl_xor_sync(0xffffffffu, s, o);
        s2 += __shfl_xor_sync(0xffffffffu, s2, o);
    }
    __shared__ float sh[16];
    int w = t >> 5, l = t & 31;
    if (l == 0) { sh[w] = s; sh[8 + w] = s2; }
    __syncthreads();
    if (t == 0) {
        float a = 0.f, c = 0.f;
#pragma unroll
        for (int i = 0; i < 8; i++) { a += sh[i]; c += sh[8 + i]; }
        sh[0] = a; sh[8] = c;
    }
    __syncthreads();
    float mu  = sh[0] * (1.0f / CC);
    float var = sh[8] * (1.0f / CC) - mu * mu;
    float inv = rsqrtf(var + 1e-5f);
#pragma unroll
    for (int i = 0; i < 4; i++) {
        int c = t + i * 256;
        out[base + c] = rnd_tf32((v[i] - mu) * inv * g[c] + b[c]);
    }
}

// ---------------------------------------------------------------------------
// gemm_cp: NT TF32 GEMM with cp.async double-buffered pipeline.
// A [M,K] row-major, B [Nc,K] row-major — BOTH pre-rounded to tf32.
// CTA tile 128x128, BK=32, 8 warps (4 along M x 2 along N), warp 32x64.
// ---------------------------------------------------------------------------
__global__ __launch_bounds__(256, 2)
void gemm_cp(const float* __restrict__ A, const float* __restrict__ Bm,
             float* __restrict__ Cc,
             int K, int lda, int ldb, int ldc,
             long long Abs, long long Ahs,
             long long Bbs, long long Bhs,
             long long Cbs, long long Chs, int Hh,
             const float* __restrict__ bias,
             const float* __restrict__ res, int act, int rnd)
{
    constexpr int LD = 36;              // words per row (144B = 9*16B, aligned)
    constexpr int ASTG = 128 * LD;      // words per A stage
    constexpr int STG = 256 * LD;       // words per (A+B) stage
    extern __shared__ unsigned sm_[];

    int zb = blockIdx.z / Hh, zh = blockIdx.z % Hh;
    A  += zb * Abs + zh * Ahs;
    Bm += zb * Bbs + zh * Bhs;
    Cc += zb * Cbs + zh * Chs;

    int t = threadIdx.x, w = t >> 5, lane = t & 31;
    int gid = lane >> 2, tig = lane & 3;
    int m0 = blockIdx.y * 128, n0 = blockIdx.x * 128;
    int wm = (w & 3) * 32, wn = (w >> 2) * 64;

    int lrow = t >> 3;        // 0..31
    int lcol = (t & 7) * 4;   // 0..28

    uint32_t sbase = smem_u32(sm_);

    auto fill = [&](int p, int k0) {
        uint32_t as = sbase + p * STG * 4;
        uint32_t bs = as + ASTG * 4;
#pragma unroll
        for (int i = 0; i < 4; i++) {
            int r = lrow + 32 * i;
            cp16(as + (r * LD + lcol) * 4,
                 &A[(long long)(m0 + r) * lda + k0 + lcol]);
            cp16(bs + (r * LD + lcol) * 4,
                 &Bm[(long long)(n0 + r) * ldb + k0 + lcol]);
        }
        asm volatile("cp.async.commit_group;" ::: "memory");
    };

    float acc[2][8][4] = {};

    fill(0, 0);
    int S = K / 32;
    for (int s = 0; s < S; s++) {
        int p = s & 1;
        if (s + 1 < S) {
            fill(p ^ 1, (s + 1) * 32);
            asm volatile("cp.async.wait_group 1;" ::: "memory");
        } else {
            asm volatile("cp.async.wait_group 0;" ::: "memory");
        }
        __syncthreads();

        const unsigned* As = sm_ + p * STG;
        const unsigned* Bs = As + ASTG;
#pragma unroll
        for (int kk = 0; kk < 32; kk += 8) {
            unsigned af[2][4], bf[8][2];
#pragma unroll
            for (int i = 0; i < 2; i++) {
                int r = wm + i * 16 + gid;
                af[i][0] = As[r * LD + kk + tig];
                af[i][1] = As[(r + 8) * LD + kk + tig];
                af[i][2] = As[r * LD + kk + tig + 4];
                af[i][3] = As[(r + 8) * LD + kk + tig + 4];
            }
#pragma unroll
            for (int j = 0; j < 8; j++) {
                int c = wn + j * 8 + gid;
                bf[j][0] = Bs[c * LD + kk + tig];
                bf[j][1] = Bs[c * LD + kk + tig + 4];
            }
#pragma unroll
            for (int i = 0; i < 2; i++)
#pragma unroll
                for (int j = 0; j < 8; j++)
                    mma_tf32(acc[i][j], af[i], bf[j]);
        }
        __syncthreads();
    }

    // epilogue
#pragma unroll
    for (int i = 0; i < 2; i++) {
        int r1 = m0 + wm + i * 16 + gid;
        int r2 = r1 + 8;
#pragma unroll
        for (int j = 0; j < 8; j++) {
            int c = n0 + wn + j * 8 + 2 * tig;
            float v0 = acc[i][j][0], v1 = acc[i][j][1];
            float v2 = acc[i][j][2], v3 = acc[i][j][3];
            if (bias) {
                float b0 = bias[c], b1 = bias[c + 1];
                v0 += b0; v1 += b1; v2 += b0; v3 += b1;
            }
            if (act) {
                v0 = gelu_exact(v0); v1 = gelu_exact(v1);
                v2 = gelu_exact(v2); v3 = gelu_exact(v3);
            }
            long long i1 = (long long)r1 * ldc + c;
            long long i2 = (long long)r2 * ldc + c;
            if (res) {
                float2 ra = *reinterpret_cast<const float2*>(&res[i1]);
                float2 rb = *reinterpret_cast<const float2*>(&res[i2]);
                v0 += ra.x; v1 += ra.y; v2 += rb.x; v3 += rb.y;
            }
            if (rnd) {
                v0 = rnd_tf32(v0); v1 = rnd_tf32(v1);
                v2 = rnd_tf32(v2); v3 = rnd_tf32(v3);
            }
            float2 o1 = {v0, v1}, o2 = {v2, v3};
            *reinterpret_cast<float2*>(&Cc[i1]) = o1;
            *reinterpret_cast<float2*>(&Cc[i2]) = o2;
        }
    }
}

// ---------------------------------------------------------------------------
// gemm_tc (legacy, in-kernel cvt): used only for AV (B non-transposed, BN=64).
// ---------------------------------------------------------------------------
template <bool BT, int BM, int BN>
__global__ __launch_bounds__(256)
void gemm_tc(const float* __restrict__ A, const float* __restrict__ Bm,
             float* __restrict__ Cc,
             int M, int Nc, int K, int lda, int ldb, int ldc,
             long long Abs, long long Ahs,
             long long Bbs, long long Bhs,
             long long Cbs, long long Chs, int Hh,
             const float* __restrict__ bias,
             const float* __restrict__ res, int act, int rnd)
{
    constexpr int BK = 32;
    constexpr int WM = BM / 4;
    constexpr int WN = BN / 2;
    constexpr int MT = WM / 16;
    constexpr int NT = WN / 8;
    constexpr int LDS_ = BK + 4;

    __shared__ unsigned As[BM][LDS_];
    __shared__ unsigned Bs[BN][LDS_];

    int zb = blockIdx.z / Hh, zh = blockIdx.z % Hh;
    A  += zb * Abs + zh * Ahs;
    Bm += zb * Bbs + zh * Bhs;
    Cc += zb * Cbs + zh * Chs;

    int t = threadIdx.x;
    int w = t >> 5, lane = t & 31;
    int gid = lane >> 2, tig = lane & 3;
    int m0 = blockIdx.y * BM, n0 = blockIdx.x * BN;
    int wm = (w & 3) * WM, wn = (w >> 2) * WN;

    float acc[MT][NT][4] = {};

    int la_col = (t & 7) * 4;
    int la_row = t >> 3;
    int lb_nc  = (t & 15) * 4;
    int lb_kr  = t >> 4;

    for (int k0 = 0; k0 < K; k0 += BK) {
#pragma unroll
        for (int r = la_row; r < BM; r += 32) {
            float4 v = *reinterpret_cast<const float4*>(
                &A[(long long)(m0 + r) * lda + k0 + la_col]);
            As[r][la_col + 0] = f2tf32(v.x);
            As[r][la_col + 1] = f2tf32(v.y);
            As[r][la_col + 2] = f2tf32(v.z);
            As[r][la_col + 3] = f2tf32(v.w);
        }
        if (BT) {
#pragma unroll
            for (int r = la_row; r < BN; r += 32) {
                float4 v = *reinterpret_cast<const float4*>(
                    &Bm[(long long)(n0 + r) * ldb + k0 + la_col]);
                Bs[r][la_col + 0] = f2tf32(v.x);
                Bs[r][la_col + 1] = f2tf32(v.y);
                Bs[r][la_col + 2] = f2tf32(v.z);
                Bs[r][la_col + 3] = f2tf32(v.w);
            }
        } else {
#pragma unroll
            for (int k2 = lb_kr; k2 < BK; k2 += 16) {
                float4 v = *reinterpret_cast<const float4*>(
                    &Bm[(long long)(k0 + k2) * ldb + n0 + lb_nc]);
                Bs[lb_nc + 0][k2] = f2tf32(v.x);
                Bs[lb_nc + 1][k2] = f2tf32(v.y);
                Bs[lb_nc + 2][k2] = f2tf32(v.z);
                Bs[lb_nc + 3][k2] = f2tf32(v.w);
            }
        }
        __syncthreads();

#pragma unroll
        for (int kk = 0; kk < BK; kk += 8) {
            unsigned af[MT][4], bf[NT][2];
#pragma unroll
            for (int i = 0; i < MT; i++) {
                int r = wm + i * 16 + gid;
                af[i][0] = As[r][kk + tig];
                af[i][1] = As[r + 8][kk + tig];
                af[i][2] = As[r][kk + tig + 4];
                af[i][3] = As[r + 8][kk + tig + 4];
            }
#pragma unroll
            for (int j = 0; j < NT; j++) {
                int c = wn + j * 8 + gid;
                bf[j][0] = Bs[c][kk + tig];
                bf[j][1] = Bs[c][kk + tig + 4];
            }
#pragma unroll
            for (int i = 0; i < MT; i++)
#pragma unroll
                for (int j = 0; j < NT; j++)
                    mma_tf32(acc[i][j], af[i], bf[j]);
        }
        __syncthreads();
    }

#pragma unroll
    for (int i = 0; i < MT; i++) {
        int r1 = m0 + wm + i * 16 + gid;
        int r2 = r1 + 8;
#pragma unroll
        for (int j = 0; j < NT; j++) {
            int c = n0 + wn + j * 8 + 2 * tig;
            float v0 = acc[i][j][0], v1 = acc[i][j][1];
            float v2 = acc[i][j][2], v3 = acc[i][j][3];
            if (bias) {
                float b0 = bias[c], b1 = bias[c + 1];
                v0 += b0; v1 += b1; v2 += b0; v3 += b1;
            }
            if (act) {
                v0 = gelu_exact(v0); v1 = gelu_exact(v1);
                v2 = gelu_exact(v2); v3 = gelu_exact(v3);
            }
            long long i1 = (long long)r1 * ldc + c;
            long long i2 = (long long)r2 * ldc + c;
            if (res) {
                float2 ra = *reinterpret_cast<const float2*>(&res[i1]);
                float2 rb = *reinterpret_cast<const float2*>(&res[i2]);
                v0 += ra.x; v1 += ra.y; v2 += rb.x; v3 += rb.y;
            }
            if (rnd) {
                v0 = rnd_tf32(v0); v1 = rnd_tf32(v1);
                v2 = rnd_tf32(v2); v3 = rnd_tf32(v3);
            }
            float2 o1 = {v0, v1}, o2 = {v2, v3};
            *reinterpret_cast<float2*>(&Cc[i1]) = o1;
            *reinterpret_cast<float2*>(&Cc[i2]) = o2;
        }
    }
}

// ---------------------------------------------------------------------------
// Softmax (in place): scale + mask + softmax, row length N=2048.
// ---------------------------------------------------------------------------
__global__ void softmax_kernel(float* __restrict__ attn,
                               const int* __restrict__ mask)
{
    long long row = blockIdx.x;
    int bidx = (int)(row / ((long long)HH * NN_));
    float* r = attn + row * NN_;
    const int* mr = mask + (long long)bidx * NN_;
    int t = threadIdx.x;

    const float scale = 0.125f;

    float v[8];
    float mx = -INFINITY;
#pragma unroll
    for (int i = 0; i < 8; i++) {
        int c = t + i * 256;
        float val = mr[c] ? r[c] * scale : -INFINITY;
        v[i] = val;
        mx = fmaxf(mx, val);
    }
#pragma unroll
    for (int o = 16; o; o >>= 1)
        mx = fmaxf(mx, __shfl_xor_sync(0xffffffffu, mx, o));

    __shared__ float shm[8], shs[8];
    int w = t >> 5, l = t & 31;
    if (l == 0) shm[w] = mx;
    __syncthreads();
    float m2 = shm[0];
#pragma unroll
    for (int i = 1; i < 8; i++) m2 = fmaxf(m2, shm[i]);

    float se = 0.f;
#pragma unroll
    for (int i = 0; i < 8; i++) {
        v[i] = expf(v[i] - m2);
        se += v[i];
    }
#pragma unroll
    for (int o = 16; o; o >>= 1)
        se += __shfl_xor_sync(0xffffffffu, se, o);
    if (l == 0) shs[w] = se;
    __syncthreads();
    float tot = 0.f;
#pragma unroll
    for (int i = 0; i < 8; i++) tot += shs[i];
    float inv = 1.0f / tot;

#pragma unroll
    for (int i = 0; i < 8; i++) {
        int c = t + i * 256;
        r[c] = v[i] * inv;
    }
}

// ---------------------------------------------------------------------------
// Launch
// ---------------------------------------------------------------------------
extern "C" void kernel_launch(void* const* d_in, const int* in_sizes, int n_in,
                              void* d_out, int out_size)
{
    const float* x      = (const float*)d_in[0];
    const int*   mask   = (const int*)  d_in[1];
    const float* qkv_w  = (const float*)d_in[2];
    const float* proj_w = (const float*)d_in[3];
    const float* proj_b = (const float*)d_in[4];
    const float* ln1_g  = (const float*)d_in[5];
    const float* ln1_b  = (const float*)d_in[6];
    const float* ln2_g  = (const float*)d_in[7];
    const float* ln2_b  = (const float*)d_in[8];
    const float* fc1_w  = (const float*)d_in[9];
    const float* fc1_b  = (const float*)d_in[10];
    const float* fc2_w  = (const float*)d_in[11];
    const float* fc2_b  = (const float*)d_in[12];

    float* out_x    = (float*)d_out;
    float* out_attn = out_x + (long long)Bb * NN_ * CC;

    float *p_ln, *p_qkv, *p_ao, *p_x1, *p_h, *p_wq, *p_wp, *p_w1, *p_w2;
    cudaGetSymbolAddress((void**)&p_ln,  g_ln);
    cudaGetSymbolAddress((void**)&p_qkv, g_qkv);
    cudaGetSymbolAddress((void**)&p_ao,  g_attnout);
    cudaGetSymbolAddress((void**)&p_x1,  g_x1);
    cudaGetSymbolAddress((void**)&p_h,   g_hbuf);
    cudaGetSymbolAddress((void**)&p_wq,  g_wq);
    cudaGetSymbolAddress((void**)&p_wp,  g_wp);
    cudaGetSymbolAddress((void**)&p_w1,  g_w1);
    cudaGetSymbolAddress((void**)&p_w2,  g_w2);

    const int M  = Bb * NN_;                 // 4096
    const long long ZERO = 0;
    const long long NC3 = (long long)NN_ * 3 * CC;
    const int SMEMCP = 2 * 256 * 36 * 4;     // 73728 bytes

    cudaFuncSetAttribute(gemm_cp, cudaFuncAttributeMaxDynamicSharedMemorySize, SMEMCP);

    // 0) pre-round weights to tf32
    rnd_kernel<<<3 * CC * CC / 1024, 256>>>(qkv_w,  p_wq, 3 * CC * CC);
    rnd_kernel<<<CC * CC / 1024,     256>>>(proj_w, p_wp, CC * CC);
    rnd_kernel<<<DFF_ * CC / 1024,   256>>>(fc1_w,  p_w1, DFF_ * CC);
    rnd_kernel<<<CC * DFF_ / 1024,   256>>>(fc2_w,  p_w2, CC * DFF_);

    // 1) LN1 (rounded output)
    ln_kernel<<<M, 256>>>(x, ln1_g, ln1_b, p_ln);

    // 2) QKV: [4096,3072] = ln @ qkv_w^T  (output rounded — feeds QK and AV)
    {
        dim3 grid(3 * CC / 128, M / 128, 1);
        gemm_cp<<<grid, 256, SMEMCP>>>(p_ln, p_wq, p_qkv,
            CC, CC, CC, 3 * CC,
            ZERO, ZERO, ZERO, ZERO, ZERO, ZERO, 1,
            nullptr, nullptr, 0, 1);
    }

    // 3) QK^T per head -> out_attn (raw logits)
    {
        dim3 grid(NN_ / 128, NN_ / 128, Bb * HH);
        gemm_cp<<<grid, 256, SMEMCP>>>(p_qkv, p_qkv + CC, out_attn,
            DD, 3 * CC, 3 * CC, NN_,
            NC3, DD, NC3, DD,
            (long long)HH * NN_ * NN_, (long long)NN_ * NN_, HH,
            nullptr, nullptr, 0, 0);
    }

    // 4) softmax (scale + mask), in place — probs NOT rounded (checked output)
    softmax_kernel<<<Bb * HH * NN_, 256>>>(out_attn, mask);

    // 5) AV per head: [2048,64] = attn @ V  (legacy cvt path; output rounded)
    {
        dim3 grid(1, NN_ / 128, Bb * HH);
        gemm_tc<false, 128, 64><<<grid, 256>>>(out_attn, p_qkv + 2 * CC, p_ao,
            NN_, DD, NN_, NN_, 3 * CC, CC,
            (long long)HH * NN_ * NN_, (long long)NN_ * NN_,
            NC3, DD,
            (long long)NN_ * CC, DD, HH,
            nullptr, nullptr, 0, 1);
    }

    // 6) proj + residual: x1 = x + ao @ proj_w^T + proj_b  (full precision out)
    {
        dim3 grid(CC / 128, M / 128, 1);
        gemm_cp<<<grid, 256, SMEMCP>>>(p_ao, p_wp, p_x1,
            CC, CC, CC, CC,
            ZERO, ZERO, ZERO, ZERO, ZERO, ZERO, 1,
            proj_b, x, 0, 0);
    }

    // 7) LN2 (rounded output)
    ln_kernel<<<M, 256>>>(p_x1, ln2_g, ln2_b, p_ln);

    // 8) FC1 + GELU (output rounded — feeds FC2)
    {
        dim3 grid(DFF_ / 128, M / 128, 1);
        gemm_cp<<<grid, 256, SMEMCP>>>(p_ln, p_w1, p_h,
            CC, CC, CC, DFF_,
            ZERO, ZERO, ZERO, ZERO, ZERO, ZERO, 1,
            fc1_b, nullptr, 1, 1);
    }

    // 9) FC2 + residual (full precision out)
    {
        dim3 grid(CC / 128, M / 128, 1);
        gemm_cp<<<grid, 256, SMEMCP>>>(p_h, p_w2, out_x,
            DFF_, DFF_, DFF_, CC,
            ZERO, ZERO, ZERO, ZERO, ZERO, ZERO, 1,
            fc2_b, p_x1, 0, 0);
    }
}

// round 7
// speedup vs baseline: 1.9802x; 1.4582x over previous
#include <cuda_runtime.h>
#include <cuda_fp16.h>
#include <math.h>
#include <stdint.h>

// Problem constants
#define Bb   2
#define NN_  2048
#define CC   1024
#define HH   16
#define DD   64
#define DFF_ 4096

// Scratch buffers (static device globals — allocation-free rule)
__device__ __half g_lnh[Bb * NN_ * CC];          // LN output (half)
__device__ __half g_qkvh[Bb * NN_ * 3 * CC];     // qkv (half)
__device__ __half g_aoh[Bb * NN_ * CC];          // attn@V repacked (half)
__device__ float  g_x1[Bb * NN_ * CC];           // x + proj (fp32)
__device__ __half g_hbufh[Bb * NN_ * DFF_];      // gelu(fc1) (half)
__device__ __half g_ph[(long long)Bb * HH * NN_ * NN_]; // probs (half copy)
// half weight copies
__device__ __half g_wq[3 * CC * CC];
__device__ __half g_wp[CC * CC];
__device__ __half g_w1[DFF_ * CC];
__device__ __half g_w2[CC * DFF_];

// ---------------------------------------------------------------------------
// helpers
// ---------------------------------------------------------------------------
__device__ __forceinline__ float gelu_exact(float v) {
    return 0.5f * v * (1.0f + erff(v * 0.70710678118654752f));
}
__device__ __forceinline__ void mma_f16(float* d, const unsigned* a, const unsigned* b) {
    asm volatile(
        "mma.sync.aligned.m16n8k16.row.col.f32.f16.f16.f32 "
        "{%0,%1,%2,%3}, {%4,%5,%6,%7}, {%8,%9}, {%0,%1,%2,%3};\n"
        : "+f"(d[0]), "+f"(d[1]), "+f"(d[2]), "+f"(d[3])
        : "r"(a[0]), "r"(a[1]), "r"(a[2]), "r"(a[3]),
          "r"(b[0]), "r"(b[1]));
}

// ---------------------------------------------------------------------------
// weight convert fp32 -> half
// ---------------------------------------------------------------------------
__global__ void h_cvt(const float* __restrict__ s, __half* __restrict__ d, int n)
{
    int i = (blockIdx.x * 256 + threadIdx.x) * 4;
    if (i < n) {
        float4 v = *reinterpret_cast<const float4*>(&s[i]);
        __half2 a = __floats2half2_rn(v.x, v.y);
        __half2 b = __floats2half2_rn(v.z, v.w);
        *reinterpret_cast<__half2*>(&d[i])     = a;
        *reinterpret_cast<__half2*>(&d[i + 2]) = b;
    }
}

// ---------------------------------------------------------------------------
// LayerNorm: fp32 in, half out (feeds GEMMs only)
// ---------------------------------------------------------------------------
__global__ void ln_kernel(const float* __restrict__ x,
                          const float* __restrict__ g,
                          const float* __restrict__ b,
                          __half* __restrict__ out)
{
    int row = blockIdx.x;
    long long base = (long long)row * CC;
    int t = threadIdx.x;

    float v[4];
    float s = 0.f, s2 = 0.f;
#pragma unroll
    for (int i = 0; i < 4; i++) {
        v[i] = x[base + t + i * 256];
        s  += v[i];
        s2 += v[i] * v[i];
    }
#pragma unroll
    for (int o = 16; o; o >>= 1) {
        s  += __shfl_xor_sync(0xffffffffu, s, o);
        s2 += __shfl_xor_sync(0xffffffffu, s2, o);
    }
    __shared__ float sh[16];
    int w = t >> 5, l = t & 31;
    if (l == 0) { sh[w] = s; sh[8 + w] = s2; }
    __syncthreads();
    if (t == 0) {
        float a = 0.f, c = 0.f;
#pragma unroll
        for (int i = 0; i < 8; i++) { a += sh[i]; c += sh[8 + i]; }
        sh[0] = a; sh[8] = c;
    }
    __syncthreads();
    float mu  = sh[0] * (1.0f / CC);
    float var = sh[8] * (1.0f / CC) - mu * mu;
    float inv = rsqrtf(var + 1e-5f);
#pragma unroll
    for (int i = 0; i < 4; i++) {
        int c = t + i * 256;
        out[base + c] = __float2half((v[i] - mu) * inv * g[c] + b[c]);
    }
}

// ---------------------------------------------------------------------------
// gemm_h: NT fp16 GEMM (A [M,K] half, B [Nc,K] half, both K-major row-major).
// CTA 128x128, BK=32, 8 warps (2 along M x 4 along N), warp 64x32.
// mma m16n8k16. Output fp32 or half (outHalf), +bias/+gelu/+residual(fp32).
// ---------------------------------------------------------------------------
__global__ __launch_bounds__(256, 2)
void gemm_h(const __half* __restrict__ A, const __half* __restrict__ Bm,
            void* __restrict__ Cv,
            int K, int lda, int ldb, int ldc,
            long long Abs, long long Ahs,
            long long Bbs, long long Bhs,
            long long Cbs, long long Chs, int Hh,
            const float* __restrict__ bias,
            const float* __restrict__ res, int act, int outHalf)
{
    constexpr int LD = 40;                    // halfs per smem row (80B)
    __shared__ __half As[128 * LD];
    __shared__ __half Bs[128 * LD];

    int zb = blockIdx.z / Hh, zh = blockIdx.z % Hh;
    A  += zb * Abs + zh * Ahs;
    Bm += zb * Bbs + zh * Bhs;

    int t = threadIdx.x, w = t >> 5, lane = t & 31;
    int gid = lane >> 2, tig = lane & 3;
    int m0 = blockIdx.y * 128, n0 = blockIdx.x * 128;
    int wm = (w & 1) * 64, wn = (w >> 1) * 32;   // warp tile 64x32: MT=4, NT=4

    int lrow = t >> 2;          // 0..63
    int lcol = (t & 3) * 8;     // 0,8,16,24 halfs

    float acc[4][4][4] = {};

    for (int k0 = 0; k0 < K; k0 += 32) {
#pragma unroll
        for (int i = 0; i < 2; i++) {
            int r = lrow + 64 * i;
            *reinterpret_cast<uint4*>(&As[r * LD + lcol]) =
                *reinterpret_cast<const uint4*>(&A[(long long)(m0 + r) * lda + k0 + lcol]);
            *reinterpret_cast<uint4*>(&Bs[r * LD + lcol]) =
                *reinterpret_cast<const uint4*>(&Bm[(long long)(n0 + r) * ldb + k0 + lcol]);
        }
        __syncthreads();

#pragma unroll
        for (int kk = 0; kk < 32; kk += 16) {
            unsigned af[4][4], bf[4][2];
#pragma unroll
            for (int i = 0; i < 4; i++) {
                int r = wm + i * 16 + gid;
                af[i][0] = *reinterpret_cast<const unsigned*>(&As[r * LD + kk + 2 * tig]);
                af[i][1] = *reinterpret_cast<const unsigned*>(&As[(r + 8) * LD + kk + 2 * tig]);
                af[i][2] = *reinterpret_cast<const unsigned*>(&As[r * LD + kk + 2 * tig + 8]);
                af[i][3] = *reinterpret_cast<const unsigned*>(&As[(r + 8) * LD + kk + 2 * tig + 8]);
            }
#pragma unroll
            for (int j = 0; j < 4; j++) {
                int c = wn + j * 8 + gid;
                bf[j][0] = *reinterpret_cast<const unsigned*>(&Bs[c * LD + kk + 2 * tig]);
                bf[j][1] = *reinterpret_cast<const unsigned*>(&Bs[c * LD + kk + 2 * tig + 8]);
            }
#pragma unroll
            for (int i = 0; i < 4; i++)
#pragma unroll
                for (int j = 0; j < 4; j++)
                    mma_f16(acc[i][j], af[i], bf[j]);
        }
        __syncthreads();
    }

    // epilogue
    float* Cf = (float*)Cv;
    __half* Ch = (__half*)Cv;
    long long coff = zb * Cbs + zh * Chs;
#pragma unroll
    for (int i = 0; i < 4; i++) {
        int r1 = m0 + wm + i * 16 + gid;
        int r2 = r1 + 8;
#pragma unroll
        for (int j = 0; j < 4; j++) {
            int c = n0 + wn + j * 8 + 2 * tig;
            float v0 = acc[i][j][0], v1 = acc[i][j][1];
            float v2 = acc[i][j][2], v3 = acc[i][j][3];
            if (bias) {
                float b0 = bias[c], b1 = bias[c + 1];
                v0 += b0; v1 += b1; v2 += b0; v3 += b1;
            }
            if (act) {
                v0 = gelu_exact(v0); v1 = gelu_exact(v1);
                v2 = gelu_exact(v2); v3 = gelu_exact(v3);
            }
            long long i1 = coff + (long long)r1 * ldc + c;
            long long i2 = coff + (long long)r2 * ldc + c;
            if (res) {
                float2 ra = *reinterpret_cast<const float2*>(&res[(long long)r1 * ldc + c]);
                float2 rb = *reinterpret_cast<const float2*>(&res[(long long)r2 * ldc + c]);
                v0 += ra.x; v1 += ra.y; v2 += rb.x; v3 += rb.y;
            }
            if (outHalf) {
                *reinterpret_cast<__half2*>(&Ch[i1]) = __floats2half2_rn(v0, v1);
                *reinterpret_cast<__half2*>(&Ch[i2]) = __floats2half2_rn(v2, v3);
            } else {
                float2 o1 = {v0, v1}, o2 = {v2, v3};
                *reinterpret_cast<float2*>(&Cf[i1]) = o1;
                *reinterpret_cast<float2*>(&Cf[i2]) = o2;
            }
        }
    }
}

// ---------------------------------------------------------------------------
// gemm_avh: AV fp16 GEMM. A = probs half [N,N] (lda), B = V half rows=m cols=d
// (ldb, needs transpose), C = half [*, ldc]. CTA 128x64, BK=32.
// 8 warps: 4 along M x 2 along N, warp 32x32: MT=2, NT=4.
// ---------------------------------------------------------------------------
__global__ __launch_bounds__(256, 2)
void gemm_avh(const __half* __restrict__ A, const __half* __restrict__ V,
              __half* __restrict__ C,
              int K, int lda, int ldb, int ldc,
              long long Abs, long long Ahs,
              long long Bbs, long long Bhs,
              long long Cbs, long long Chs, int Hh)
{
    constexpr int LD = 40;
    __shared__ __half As[128 * LD];
    __shared__ __half Bs[64 * LD];

    int zb = blockIdx.z / Hh, zh = blockIdx.z % Hh;
    A += zb * Abs + zh * Ahs;
    V += zb * Bbs + zh * Bhs;
    C += zb * Cbs + zh * Chs;

    int t = threadIdx.x, w = t >> 5, lane = t & 31;
    int gid = lane >> 2, tig = lane & 3;
    int m0 = blockIdx.y * 128;
    int wm = (w & 3) * 32, wn = (w >> 2) * 32;

    int lrow = t >> 2;          // 0..63
    int lcol = (t & 3) * 8;
    int vmr = t >> 3;           // 0..31 (V row within BK)
    int vdc = (t & 7) * 8;      // 0..56 (d col)

    float acc[2][4][4] = {};

    for (int k0 = 0; k0 < K; k0 += 32) {
        // A tile 128x32
#pragma unroll
        for (int i = 0; i < 2; i++) {
            int r = lrow + 64 * i;
            *reinterpret_cast<uint4*>(&As[r * LD + lcol]) =
                *reinterpret_cast<const uint4*>(&A[(long long)(m0 + r) * lda + k0 + lcol]);
        }
        // V tile 32x64 -> transposed Bs[d][m]
        {
            uint4 u = *reinterpret_cast<const uint4*>(&V[(long long)(k0 + vmr) * ldb + vdc]);
            const __half* hv = reinterpret_cast<const __half*>(&u);
#pragma unroll
            for (int j = 0; j < 8; j++)
                Bs[(vdc + j) * LD + vmr] = hv[j];
        }
        __syncthreads();

#pragma unroll
        for (int kk = 0; kk < 32; kk += 16) {
            unsigned af[2][4], bf[4][2];
#pragma unroll
            for (int i = 0; i < 2; i++) {
                int r = wm + i * 16 + gid;
                af[i][0] = *reinterpret_cast<const unsigned*>(&As[r * LD + kk + 2 * tig]);
                af[i][1] = *reinterpret_cast<const unsigned*>(&As[(r + 8) * LD + kk + 2 * tig]);
                af[i][2] = *reinterpret_cast<const unsigned*>(&As[r * LD + kk + 2 * tig + 8]);
                af[i][3] = *reinterpret_cast<const unsigned*>(&As[(r + 8) * LD + kk + 2 * tig + 8]);
            }
#pragma unroll
            for (int j = 0; j < 4; j++) {
                int c = wn + j * 8 + gid;
                bf[j][0] = *reinterpret_cast<const unsigned*>(&Bs[c * LD + kk + 2 * tig]);
                bf[j][1] = *reinterpret_cast<const unsigned*>(&Bs[c * LD + kk + 2 * tig + 8]);
            }
#pragma unroll
            for (int i = 0; i < 2; i++)
#pragma unroll
                for (int j = 0; j < 4; j++)
                    mma_f16(acc[i][j], af[i], bf[j]);
        }
        __syncthreads();
    }

#pragma unroll
    for (int i = 0; i < 2; i++) {
        int r1 = m0 + wm + i * 16 + gid;
        int r2 = r1 + 8;
#pragma unroll
        for (int j = 0; j < 4; j++) {
            int c = wn + j * 8 + 2 * tig;
            *reinterpret_cast<__half2*>(&C[(long long)r1 * ldc + c]) =
                __floats2half2_rn(acc[i][j][0], acc[i][j][1]);
            *reinterpret_cast<__half2*>(&C[(long long)r2 * ldc + c]) =
                __floats2half2_rn(acc[i][j][2], acc[i][j][3]);
        }
    }
}

// ---------------------------------------------------------------------------
// Softmax (in place on fp32 logits): scale + mask + softmax; also writes half
// probs copy for the AV GEMM. Row length N=2048.
// ---------------------------------------------------------------------------
__global__ void softmax_kernel(float* __restrict__ attn,
                               const int* __restrict__ mask,
                               __half* __restrict__ ph)
{
    long long row = blockIdx.x;
    int bidx = (int)(row / ((long long)HH * NN_));
    float* r = attn + row * NN_;
    __half* rh = ph + row * NN_;
    const int* mr = mask + (long long)bidx * NN_;
    int t = threadIdx.x;

    const float scale = 0.125f;

    float v[8];
    float mx = -INFINITY;
#pragma unroll
    for (int i = 0; i < 8; i++) {
        int c = t + i * 256;
        float val = mr[c] ? r[c] * scale : -INFINITY;
        v[i] = val;
        mx = fmaxf(mx, val);
    }
#pragma unroll
    for (int o = 16; o; o >>= 1)
        mx = fmaxf(mx, __shfl_xor_sync(0xffffffffu, mx, o));

    __shared__ float shm[8], shs[8];
    int w = t >> 5, l = t & 31;
    if (l == 0) shm[w] = mx;
    __syncthreads();
    float m2 = shm[0];
#pragma unroll
    for (int i = 1; i < 8; i++) m2 = fmaxf(m2, shm[i]);

    float se = 0.f;
#pragma unroll
    for (int i = 0; i < 8; i++) {
        v[i] = expf(v[i] - m2);
        se += v[i];
    }
#pragma unroll
    for (int o = 16; o; o >>= 1)
        se += __shfl_xor_sync(0xffffffffu, se, o);
    if (l == 0) shs[w] = se;
    __syncthreads();
    float tot = 0.f;
#pragma unroll
    for (int i = 0; i < 8; i++) tot += shs[i];
    float inv = 1.0f / tot;

#pragma unroll
    for (int i = 0; i < 8; i++) {
        int c = t + i * 256;
        float p = v[i] * inv;
        r[c] = p;
        rh[c] = __float2half(p);
    }
}

// ---------------------------------------------------------------------------
// Launch
// ---------------------------------------------------------------------------
extern "C" void kernel_launch(void* const* d_in, const int* in_sizes, int n_in,
                              void* d_out, int out_size)
{
    const float* x      = (const float*)d_in[0];
    const int*   mask   = (const int*)  d_in[1];
    const float* qkv_w  = (const float*)d_in[2];
    const float* proj_w = (const float*)d_in[3];
    const float* proj_b = (const float*)d_in[4];
    const float* ln1_g  = (const float*)d_in[5];
    const float* ln1_b  = (const float*)d_in[6];
    const float* ln2_g  = (const float*)d_in[7];
    const float* ln2_b  = (const float*)d_in[8];
    const float* fc1_w  = (const float*)d_in[9];
    const float* fc1_b  = (const float*)d_in[10];
    const float* fc2_w  = (const float*)d_in[11];
    const float* fc2_b  = (const float*)d_in[12];

    float* out_x    = (float*)d_out;
    float* out_attn = out_x + (long long)Bb * NN_ * CC;

    __half *p_ln, *p_qkv, *p_ao, *p_h, *p_ph, *p_wq, *p_wp, *p_w1, *p_w2;
    float *p_x1;
    cudaGetSymbolAddress((void**)&p_ln,  g_lnh);
    cudaGetSymbolAddress((void**)&p_qkv, g_qkvh);
    cudaGetSymbolAddress((void**)&p_ao,  g_aoh);
    cudaGetSymbolAddress((void**)&p_x1,  g_x1);
    cudaGetSymbolAddress((void**)&p_h,   g_hbufh);
    cudaGetSymbolAddress((void**)&p_ph,  g_ph);
    cudaGetSymbolAddress((void**)&p_wq,  g_wq);
    cudaGetSymbolAddress((void**)&p_wp,  g_wp);
    cudaGetSymbolAddress((void**)&p_w1,  g_w1);
    cudaGetSymbolAddress((void**)&p_w2,  g_w2);

    const int M  = Bb * NN_;                 // 4096
    const long long ZERO = 0;
    const long long NC3 = (long long)NN_ * 3 * CC;

    // 0) weights -> half
    h_cvt<<<3 * CC * CC / 1024, 256>>>(qkv_w,  p_wq, 3 * CC * CC);
    h_cvt<<<CC * CC / 1024,     256>>>(proj_w, p_wp, CC * CC);
    h_cvt<<<DFF_ * CC / 1024,   256>>>(fc1_w,  p_w1, DFF_ * CC);
    h_cvt<<<CC * DFF_ / 1024,   256>>>(fc2_w,  p_w2, CC * DFF_);

    // 1) LN1 -> half
    ln_kernel<<<M, 256>>>(x, ln1_g, ln1_b, p_ln);

    // 2) QKV: [4096,3072](half) = ln @ qkv_w^T
    {
        dim3 grid(3 * CC / 128, M / 128, 1);
        gemm_h<<<grid, 256>>>(p_ln, p_wq, p_qkv,
            CC, CC, CC, 3 * CC,
            ZERO, ZERO, ZERO, ZERO, ZERO, ZERO, 1,
            nullptr, nullptr, 0, 1);
    }

    // 3) QK^T per head -> out_attn (fp32 raw logits)
    {
        dim3 grid(NN_ / 128, NN_ / 128, Bb * HH);
        gemm_h<<<grid, 256>>>(p_qkv, p_qkv + CC, out_attn,
            DD, 3 * CC, 3 * CC, NN_,
            NC3, DD, NC3, DD,
            (long long)HH * NN_ * NN_, (long long)NN_ * NN_, HH,
            nullptr, nullptr, 0, 0);
    }

    // 4) softmax (scale + mask), fp32 in place + half copy
    softmax_kernel<<<Bb * HH * NN_, 256>>>(out_attn, mask, p_ph);

    // 5) AV per head (fp16): [2048,64] = probs_h @ V
    {
        dim3 grid(1, NN_ / 128, Bb * HH);
        gemm_avh<<<grid, 256>>>(p_ph, p_qkv + 2 * CC, p_ao,
            NN_, NN_, 3 * CC, CC,
            (long long)HH * NN_ * NN_, (long long)NN_ * NN_,
            NC3, DD,
            (long long)NN_ * CC, DD, HH);
    }

    // 6) proj + residual: x1(fp32) = x + ao @ proj_w^T + proj_b
    {
        dim3 grid(CC / 128, M / 128, 1);
        gemm_h<<<grid, 256>>>(p_ao, p_wp, p_x1,
            CC, CC, CC, CC,
            ZERO, ZERO, ZERO, ZERO, ZERO, ZERO, 1,
            proj_b, x, 0, 0);
    }

    // 7) LN2 -> half
    ln_kernel<<<M, 256>>>(p_x1, ln2_g, ln2_b, p_ln);

    // 8) FC1 + GELU -> half
    {
        dim3 grid(DFF_ / 128, M / 128, 1);
        gemm_h<<<grid, 256>>>(p_ln, p_w1, p_h,
            CC, CC, CC, DFF_,
            ZERO, ZERO, ZERO, ZERO, ZERO, ZERO, 1,
            fc1_b, nullptr, 1, 1);
    }

    // 9) FC2 + residual -> out_x (fp32)
    {
        dim3 grid(CC / 128, M / 128, 1);
        gemm_h<<<grid, 256>>>(p_h, p_w2, out_x,
            DFF_, DFF_, DFF_, CC,
            ZERO, ZERO, ZERO, ZERO, ZERO, ZERO, 1,
            fc2_b, p_x1, 0, 0);
    }
}

// round 8
// speedup vs baseline: 2.0684x; 1.0445x over previous
#include <cuda_runtime.h>
#include <cuda_fp16.h>
#include <math.h>
#include <stdint.h>

// Problem constants
#define Bb   2
#define NN_  2048
#define CC   1024
#define HH   16
#define DD   64
#define DFF_ 4096

// Scratch buffers (static device globals — allocation-free rule)
__device__ __half g_lnh[Bb * NN_ * CC];
__device__ __half g_qkvh[Bb * NN_ * 3 * CC];
__device__ __half g_aoh[Bb * NN_ * CC];
__device__ float  g_x1[Bb * NN_ * CC];
__device__ __half g_hbufh[Bb * NN_ * DFF_];
__device__ __half g_ph[(long long)Bb * HH * NN_ * NN_];
__device__ __half g_wq[3 * CC * CC];
__device__ __half g_wp[CC * CC];
__device__ __half g_w1[DFF_ * CC];
__device__ __half g_w2[CC * DFF_];

// ---------------------------------------------------------------------------
// helpers
// ---------------------------------------------------------------------------
__device__ __forceinline__ float gelu_exact(float v) {
    return 0.5f * v * (1.0f + erff(v * 0.70710678118654752f));
}
__device__ __forceinline__ uint32_t smem_u32(const void* p) {
    uint32_t a;
    asm("{ .reg .u64 t; cvta.to.shared.u64 t, %1; cvt.u32.u64 %0, t; }"
        : "=r"(a) : "l"(p));
    return a;
}
__device__ __forceinline__ void cp16(uint32_t dst, const void* src) {
    asm volatile("cp.async.cg.shared.global [%0], [%1], 16;"
                 :: "r"(dst), "l"(src) : "memory");
}
__device__ __forceinline__ void mma_f16(float* d, const unsigned* a, const unsigned* b) {
    asm volatile(
        "mma.sync.aligned.m16n8k16.row.col.f32.f16.f16.f32 "
        "{%0,%1,%2,%3}, {%4,%5,%6,%7}, {%8,%9}, {%0,%1,%2,%3};\n"
        : "+f"(d[0]), "+f"(d[1]), "+f"(d[2]), "+f"(d[3])
        : "r"(a[0]), "r"(a[1]), "r"(a[2]), "r"(a[3]),
          "r"(b[0]), "r"(b[1]));
}
__device__ __forceinline__ void ldm_x4(unsigned& r0, unsigned& r1,
                                       unsigned& r2, unsigned& r3, uint32_t a) {
    asm volatile("ldmatrix.sync.aligned.m8n8.x4.shared.b16 {%0,%1,%2,%3}, [%4];"
                 : "=r"(r0), "=r"(r1), "=r"(r2), "=r"(r3) : "r"(a));
}

// ---------------------------------------------------------------------------
// weight convert fp32 -> half
// ---------------------------------------------------------------------------
__global__ void h_cvt(const float* __restrict__ s, __half* __restrict__ d, int n)
{
    int i = (blockIdx.x * 256 + threadIdx.x) * 4;
    if (i < n) {
        float4 v = *reinterpret_cast<const float4*>(&s[i]);
        *reinterpret_cast<__half2*>(&d[i])     = __floats2half2_rn(v.x, v.y);
        *reinterpret_cast<__half2*>(&d[i + 2]) = __floats2half2_rn(v.z, v.w);
    }
}

// ---------------------------------------------------------------------------
// LayerNorm: fp32 in, half out
// ---------------------------------------------------------------------------
__global__ void ln_kernel(const float* __restrict__ x,
                          const float* __restrict__ g,
                          const float* __restrict__ b,
                          __half* __restrict__ out)
{
    int row = blockIdx.x;
    long long base = (long long)row * CC;
    int t = threadIdx.x;

    float v[4];
    float s = 0.f, s2 = 0.f;
#pragma unroll
    for (int i = 0; i < 4; i++) {
        v[i] = x[base + t + i * 256];
        s  += v[i];
        s2 += v[i] * v[i];
    }
#pragma unroll
    for (int o = 16; o; o >>= 1) {
        s  += __shfl_xor_sync(0xffffffffu, s, o);
        s2 += __shfl_xor_sync(0xffffffffu, s2, o);
    }
    __shared__ float sh[16];
    int w = t >> 5, l = t & 31;
    if (l == 0) { sh[w] = s; sh[8 + w] = s2; }
    __syncthreads();
    if (t == 0) {
        float a = 0.f, c = 0.f;
#pragma unroll
        for (int i = 0; i < 8; i++) { a += sh[i]; c += sh[8 + i]; }
        sh[0] = a; sh[8] = c;
    }
    __syncthreads();
    float mu  = sh[0] * (1.0f / CC);
    float var = sh[8] * (1.0f / CC) - mu * mu;
    float inv = rsqrtf(var + 1e-5f);
#pragma unroll
    for (int i = 0; i < 4; i++) {
        int c = t + i * 256;
        out[base + c] = __float2half((v[i] - mu) * inv * g[c] + b[c]);
    }
}

// ---------------------------------------------------------------------------
// gemm_h: NT fp16 GEMM with cp.async double-buffer + ldmatrix fragments.
// A [M,K] half, B [Nc,K] half (both K-major). CTA 128x128, BK=32,
// 8 warps (2Mx4N), warp 64x32 (MT=4, NT=4).
// ---------------------------------------------------------------------------
__global__ __launch_bounds__(256, 2)
void gemm_h(const __half* __restrict__ A, const __half* __restrict__ Bm,
            void* __restrict__ Cv,
            int K, int lda, int ldb, int ldc,
            long long Abs, long long Ahs,
            long long Bbs, long long Bhs,
            long long Cbs, long long Chs, int Hh,
            const float* __restrict__ bias,
            const float* __restrict__ res, int act, int outHalf)
{
    constexpr int LD = 40;                        // halfs per smem row (80B)
    constexpr int ROWB = LD * 2;                  // bytes per row
    constexpr int ASTG_B = 128 * ROWB;            // A stage bytes (10240)
    constexpr int STG_B = 2 * ASTG_B;             // A+B stage bytes (20480)
    __shared__ __half smh[2 * 256 * LD];          // 40960 B

    int zb = blockIdx.z / Hh, zh = blockIdx.z % Hh;
    A  += zb * Abs + zh * Ahs;
    Bm += zb * Bbs + zh * Bhs;

    int t = threadIdx.x, w = t >> 5, lane = t & 31;
    int gid = lane >> 2, tig = lane & 3;
    int m0 = blockIdx.y * 128, n0 = blockIdx.x * 128;
    int wm = (w & 1) * 64, wn = (w >> 1) * 32;

    uint32_t sbase = smem_u32(smh);

    // cp.async fill indexing: 256 threads, A tile 128 rows x 4 chunks (16B),
    // B same. thread -> (row = t>>1, chunkpair): each thread does 2 chunks A + 2 B.
    int frow = t >> 1;               // 0..127
    int fch  = (t & 1) * 2;          // chunk 0 or 2 (does 2 consecutive)

    auto fill = [&](int p, int k0) {
        uint32_t as = sbase + p * STG_B;
        uint32_t bs = as + ASTG_B;
#pragma unroll
        for (int c = 0; c < 2; c++) {
            int ch = fch + c;        // 16B chunk index 0..3 -> halfs ch*8
            cp16(as + frow * ROWB + ch * 16,
                 &A[(long long)(m0 + frow) * lda + k0 + ch * 8]);
            cp16(bs + frow * ROWB + ch * 16,
                 &Bm[(long long)(n0 + frow) * ldb + k0 + ch * 8]);
        }
        asm volatile("cp.async.commit_group;" ::: "memory");
    };

    float acc[4][4][4] = {};

    fill(0, 0);
    int S = K / 32;
    for (int s = 0; s < S; s++) {
        int p = s & 1;
        if (s + 1 < S) {
            fill(p ^ 1, (s + 1) * 32);
            asm volatile("cp.async.wait_group 1;" ::: "memory");
        } else {
            asm volatile("cp.async.wait_group 0;" ::: "memory");
        }
        __syncthreads();

        uint32_t as = sbase + p * STG_B;
        uint32_t bs = as + ASTG_B;
#pragma unroll
        for (int kk = 0; kk < 32; kk += 16) {
            unsigned af[4][4], bf[4][2];
            // A fragments: 4 x ldmatrix.x4
            int arow_l = (lane & 15);
            int akoff = kk + ((lane >> 4) << 3);
#pragma unroll
            for (int i = 0; i < 4; i++) {
                uint32_t addr = as + (wm + i * 16 + arow_l) * ROWB + akoff * 2;
                ldm_x4(af[i][0], af[i][1], af[i][2], af[i][3], addr);
            }
            // B fragments: 2 x ldmatrix.x4 (each covers two n8 tiles)
            int bj = (lane >> 4) & 1;           // which n8 of the pair
            int bkoff = kk + (((lane >> 3) & 1) << 3);
            int brow_l = lane & 7;
#pragma unroll
            for (int jp = 0; jp < 2; jp++) {
                uint32_t addr = bs + (wn + (jp * 2 + bj) * 8 + brow_l) * ROWB + bkoff * 2;
                ldm_x4(bf[jp * 2][0], bf[jp * 2][1],
                       bf[jp * 2 + 1][0], bf[jp * 2 + 1][1], addr);
            }
#pragma unroll
            for (int i = 0; i < 4; i++)
#pragma unroll
                for (int j = 0; j < 4; j++)
                    mma_f16(acc[i][j], af[i], bf[j]);
        }
        __syncthreads();
    }

    // epilogue
    float* Cf = (float*)Cv;
    __half* Ch = (__half*)Cv;
    long long coff = zb * Cbs + zh * Chs;
#pragma unroll
    for (int i = 0; i < 4; i++) {
        int r1 = m0 + wm + i * 16 + gid;
        int r2 = r1 + 8;
#pragma unroll
        for (int j = 0; j < 4; j++) {
            int c = n0 + wn + j * 8 + 2 * tig;
            float v0 = acc[i][j][0], v1 = acc[i][j][1];
            float v2 = acc[i][j][2], v3 = acc[i][j][3];
            if (bias) {
                float b0 = bias[c], b1 = bias[c + 1];
                v0 += b0; v1 += b1; v2 += b0; v3 += b1;
            }
            if (act) {
                v0 = gelu_exact(v0); v1 = gelu_exact(v1);
                v2 = gelu_exact(v2); v3 = gelu_exact(v3);
            }
            long long i1 = coff + (long long)r1 * ldc + c;
            long long i2 = coff + (long long)r2 * ldc + c;
            if (res) {
                float2 ra = *reinterpret_cast<const float2*>(&res[(long long)r1 * ldc + c]);
                float2 rb = *reinterpret_cast<const float2*>(&res[(long long)r2 * ldc + c]);
                v0 += ra.x; v1 += ra.y; v2 += rb.x; v3 += rb.y;
            }
            if (outHalf) {
                *reinterpret_cast<__half2*>(&Ch[i1]) = __floats2half2_rn(v0, v1);
                *reinterpret_cast<__half2*>(&Ch[i2]) = __floats2half2_rn(v2, v3);
            } else {
                float2 o1 = {v0, v1}, o2 = {v2, v3};
                *reinterpret_cast<float2*>(&Cf[i1]) = o1;
                *reinterpret_cast<float2*>(&Cf[i2]) = o2;
            }
        }
    }
}

// ---------------------------------------------------------------------------
// gemm_avh: AV fp16 GEMM (probs @ V). A [N,N] half, V rows=k cols=d half
// (transposed into smem). CTA 128x64, BK=32, 8 warps (4Mx2N), warp 32x32.
// ldmatrix fragments.
// ---------------------------------------------------------------------------
__global__ __launch_bounds__(256, 2)
void gemm_avh(const __half* __restrict__ A, const __half* __restrict__ V,
              __half* __restrict__ C,
              int K, int lda, int ldb, int ldc,
              long long Abs, long long Ahs,
              long long Bbs, long long Bhs,
              long long Cbs, long long Chs, int Hh)
{
    constexpr int LD = 40;
    constexpr int ROWB = LD * 2;
    __shared__ __half As[128 * LD];
    __shared__ __half Bs[64 * LD];

    int zb = blockIdx.z / Hh, zh = blockIdx.z % Hh;
    A += zb * Abs + zh * Ahs;
    V += zb * Bbs + zh * Bhs;
    C += zb * Cbs + zh * Chs;

    int t = threadIdx.x, w = t >> 5, lane = t & 31;
    int gid = lane >> 2, tig = lane & 3;
    int m0 = blockIdx.y * 128;
    int wm = (w & 3) * 32, wn = (w >> 2) * 32;

    int lrow = t >> 2;          // 0..63
    int lcol = (t & 3) * 8;
    int vmr = t >> 3;           // 0..31
    int vdc = (t & 7) * 8;      // 0..56

    uint32_t asb = smem_u32(As);
    uint32_t bsb = smem_u32(Bs);

    float acc[2][4][4] = {};

    for (int k0 = 0; k0 < K; k0 += 32) {
#pragma unroll
        for (int i = 0; i < 2; i++) {
            int r = lrow + 64 * i;
            *reinterpret_cast<uint4*>(&As[r * LD + lcol]) =
                *reinterpret_cast<const uint4*>(&A[(long long)(m0 + r) * lda + k0 + lcol]);
        }
        {
            uint4 u = *reinterpret_cast<const uint4*>(&V[(long long)(k0 + vmr) * ldb + vdc]);
            const __half* hv = reinterpret_cast<const __half*>(&u);
#pragma unroll
            for (int j = 0; j < 8; j++)
                Bs[(vdc + j) * LD + vmr] = hv[j];
        }
        __syncthreads();

#pragma unroll
        for (int kk = 0; kk < 32; kk += 16) {
            unsigned af[2][4], bf[4][2];
            int arow_l = (lane & 15);
            int akoff = kk + ((lane >> 4) << 3);
#pragma unroll
            for (int i = 0; i < 2; i++) {
                uint32_t addr = asb + (wm + i * 16 + arow_l) * ROWB + akoff * 2;
                ldm_x4(af[i][0], af[i][1], af[i][2], af[i][3], addr);
            }
            int bj = (lane >> 4) & 1;
            int bkoff = kk + (((lane >> 3) & 1) << 3);
            int brow_l = lane & 7;
#pragma unroll
            for (int jp = 0; jp < 2; jp++) {
                uint32_t addr = bsb + (wn + (jp * 2 + bj) * 8 + brow_l) * ROWB + bkoff * 2;
                ldm_x4(bf[jp * 2][0], bf[jp * 2][1],
                       bf[jp * 2 + 1][0], bf[jp * 2 + 1][1], addr);
            }
#pragma unroll
            for (int i = 0; i < 2; i++)
#pragma unroll
                for (int j = 0; j < 4; j++)
                    mma_f16(acc[i][j], af[i], bf[j]);
        }
        __syncthreads();
    }

#pragma unroll
    for (int i = 0; i < 2; i++) {
        int r1 = m0 + wm + i * 16 + gid;
        int r2 = r1 + 8;
#pragma unroll
        for (int j = 0; j < 4; j++) {
            int c = wn + j * 8 + 2 * tig;
            *reinterpret_cast<__half2*>(&C[(long long)r1 * ldc + c]) =
                __floats2half2_rn(acc[i][j][0], acc[i][j][1]);
            *reinterpret_cast<__half2*>(&C[(long long)r2 * ldc + c]) =
                __floats2half2_rn(acc[i][j][2], acc[i][j][3]);
        }
    }
}

// ---------------------------------------------------------------------------
// Softmax: scale + mask + softmax, fp32 in place + half copy.
// ---------------------------------------------------------------------------
__global__ void softmax_kernel(float* __restrict__ attn,
                               const int* __restrict__ mask,
                               __half* __restrict__ ph)
{
    long long row = blockIdx.x;
    int bidx = (int)(row / ((long long)HH * NN_));
    float* r = attn + row * NN_;
    __half* rh = ph + row * NN_;
    const int* mr = mask + (long long)bidx * NN_;
    int t = threadIdx.x;

    const float scale = 0.125f;

    float v[8];
    float mx = -INFINITY;
#pragma unroll
    for (int i = 0; i < 8; i++) {
        int c = t + i * 256;
        float val = mr[c] ? r[c] * scale : -INFINITY;
        v[i] = val;
        mx = fmaxf(mx, val);
    }
#pragma unroll
    for (int o = 16; o; o >>= 1)
        mx = fmaxf(mx, __shfl_xor_sync(0xffffffffu, mx, o));

    __shared__ float shm[8], shs[8];
    int w = t >> 5, l = t & 31;
    if (l == 0) shm[w] = mx;
    __syncthreads();
    float m2 = shm[0];
#pragma unroll
    for (int i = 1; i < 8; i++) m2 = fmaxf(m2, shm[i]);

    float se = 0.f;
#pragma unroll
    for (int i = 0; i < 8; i++) {
        v[i] = expf(v[i] - m2);
        se += v[i];
    }
#pragma unroll
    for (int o = 16; o; o >>= 1)
        se += __shfl_xor_sync(0xffffffffu, se, o);
    if (l == 0) shs[w] = se;
    __syncthreads();
    float tot = 0.f;
#pragma unroll
    for (int i = 0; i < 8; i++) tot += shs[i];
    float inv = 1.0f / tot;

#pragma unroll
    for (int i = 0; i < 8; i++) {
        int c = t + i * 256;
        float p = v[i] * inv;
        r[c] = p;
        rh[c] = __float2half(p);
    }
}

// ---------------------------------------------------------------------------
// Launch
// ---------------------------------------------------------------------------
extern "C" void kernel_launch(void* const* d_in, const int* in_sizes, int n_in,
                              void* d_out, int out_size)
{
    const float* x      = (const float*)d_in[0];
    const int*   mask   = (const int*)  d_in[1];
    const float* qkv_w  = (const float*)d_in[2];
    const float* proj_w = (const float*)d_in[3];
    const float* proj_b = (const float*)d_in[4];
    const float* ln1_g  = (const float*)d_in[5];
    const float* ln1_b  = (const float*)d_in[6];
    const float* ln2_g  = (const float*)d_in[7];
    const float* ln2_b  = (const float*)d_in[8];
    const float* fc1_w  = (const float*)d_in[9];
    const float* fc1_b  = (const float*)d_in[10];
    const float* fc2_w  = (const float*)d_in[11];
    const float* fc2_b  = (const float*)d_in[12];

    float* out_x    = (float*)d_out;
    float* out_attn = out_x + (long long)Bb * NN_ * CC;

    __half *p_ln, *p_qkv, *p_ao, *p_h, *p_ph, *p_wq, *p_wp, *p_w1, *p_w2;
    float *p_x1;
    cudaGetSymbolAddress((void**)&p_ln,  g_lnh);
    cudaGetSymbolAddress((void**)&p_qkv, g_qkvh);
    cudaGetSymbolAddress((void**)&p_ao,  g_aoh);
    cudaGetSymbolAddress((void**)&p_x1,  g_x1);
    cudaGetSymbolAddress((void**)&p_h,   g_hbufh);
    cudaGetSymbolAddress((void**)&p_ph,  g_ph);
    cudaGetSymbolAddress((void**)&p_wq,  g_wq);
    cudaGetSymbolAddress((void**)&p_wp,  g_wp);
    cudaGetSymbolAddress((void**)&p_w1,  g_w1);
    cudaGetSymbolAddress((void**)&p_w2,  g_w2);

    const int M  = Bb * NN_;                 // 4096
    const long long ZERO = 0;
    const long long NC3 = (long long)NN_ * 3 * CC;

    // 0) weights -> half
    h_cvt<<<3 * CC * CC / 1024, 256>>>(qkv_w,  p_wq, 3 * CC * CC);
    h_cvt<<<CC * CC / 1024,     256>>>(proj_w, p_wp, CC * CC);
    h_cvt<<<DFF_ * CC / 1024,   256>>>(fc1_w,  p_w1, DFF_ * CC);
    h_cvt<<<CC * DFF_ / 1024,   256>>>(fc2_w,  p_w2, CC * DFF_);

    // 1) LN1 -> half
    ln_kernel<<<M, 256>>>(x, ln1_g, ln1_b, p_ln);

    // 2) QKV
    {
        dim3 grid(3 * CC / 128, M / 128, 1);
        gemm_h<<<grid, 256>>>(p_ln, p_wq, p_qkv,
            CC, CC, CC, 3 * CC,
            ZERO, ZERO, ZERO, ZERO, ZERO, ZERO, 1,
            nullptr, nullptr, 0, 1);
    }

    // 3) QK^T per head -> out_attn (fp32 raw logits)
    {
        dim3 grid(NN_ / 128, NN_ / 128, Bb * HH);
        gemm_h<<<grid, 256>>>(p_qkv, p_qkv + CC, out_attn,
            DD, 3 * CC, 3 * CC, NN_,
            NC3, DD, NC3, DD,
            (long long)HH * NN_ * NN_, (long long)NN_ * NN_, HH,
            nullptr, nullptr, 0, 0);
    }

    // 4) softmax
    softmax_kernel<<<Bb * HH * NN_, 256>>>(out_attn, mask, p_ph);

    // 5) AV per head
    {
        dim3 grid(1, NN_ / 128, Bb * HH);
        gemm_avh<<<grid, 256>>>(p_ph, p_qkv + 2 * CC, p_ao,
            NN_, NN_, 3 * CC, CC,
            (long long)HH * NN_ * NN_, (long long)NN_ * NN_,
            NC3, DD,
            (long long)NN_ * CC, DD, HH);
    }

    // 6) proj + residual -> x1 (fp32)
    {
        dim3 grid(CC / 128, M / 128, 1);
        gemm_h<<<grid, 256>>>(p_ao, p_wp, p_x1,
            CC, CC, CC, CC,
            ZERO, ZERO, ZERO, ZERO, ZERO, ZERO, 1,
            proj_b, x, 0, 0);
    }

    // 7) LN2 -> half
    ln_kernel<<<M, 256>>>(p_x1, ln2_g, ln2_b, p_ln);

    // 8) FC1 + GELU -> half
    {
        dim3 grid(DFF_ / 128, M / 128, 1);
        gemm_h<<<grid, 256>>>(p_ln, p_w1, p_h,
            CC, CC, CC, DFF_,
            ZERO, ZERO, ZERO, ZERO, ZERO, ZERO, 1,
            fc1_b, nullptr, 1, 1);
    }

    // 9) FC2 + residual -> out_x (fp32)
    {
        dim3 grid(CC / 128, M / 128, 1);
        gemm_h<<<grid, 256>>>(p_h, p_w2, out_x,
            DFF_, DFF_, DFF_, CC,
            ZERO, ZERO, ZERO, ZERO, ZERO, ZERO, 1,
            fc2_b, p_x1, 0, 0);
    }
}

// round 9
// speedup vs baseline: 2.1061x; 1.0182x over previous
#include <cuda_runtime.h>
#include <cuda_fp16.h>
#include <math.h>
#include <stdint.h>

// Problem constants
#define Bb   2
#define NN_  2048
#define CC   1024
#define HH   16
#define DD   64
#define DFF_ 4096

// Scratch buffers (static device globals — allocation-free rule)
__device__ __half g_lnh[Bb * NN_ * CC];
__device__ __half g_qkvh[Bb * NN_ * 3 * CC];
__device__ __half g_aoh[Bb * NN_ * CC];
__device__ float  g_x1[Bb * NN_ * CC];
__device__ __half g_hbufh[Bb * NN_ * DFF_];
__device__ __half g_ph[(long long)Bb * HH * NN_ * NN_];  // unnormalized exp (half)
__device__ float  g_invs[Bb * HH * NN_];                 // 1/rowsum
__device__ __half g_wq[3 * CC * CC];
__device__ __half g_wp[CC * CC];
__device__ __half g_w1[DFF_ * CC];
__device__ __half g_w2[CC * DFF_];

// ---------------------------------------------------------------------------
// helpers
// ---------------------------------------------------------------------------
__device__ __forceinline__ float gelu_exact(float v) {
    return 0.5f * v * (1.0f + erff(v * 0.70710678118654752f));
}
__device__ __forceinline__ uint32_t smem_u32(const void* p) {
    uint32_t a;
    asm("{ .reg .u64 t; cvta.to.shared.u64 t, %1; cvt.u32.u64 %0, t; }"
        : "=r"(a) : "l"(p));
    return a;
}
__device__ __forceinline__ void cp16(uint32_t dst, const void* src) {
    asm volatile("cp.async.cg.shared.global [%0], [%1], 16;"
                 :: "r"(dst), "l"(src) : "memory");
}
__device__ __forceinline__ void mma_f16(float* d, const unsigned* a, const unsigned* b) {
    asm volatile(
        "mma.sync.aligned.m16n8k16.row.col.f32.f16.f16.f32 "
        "{%0,%1,%2,%3}, {%4,%5,%6,%7}, {%8,%9}, {%0,%1,%2,%3};\n"
        : "+f"(d[0]), "+f"(d[1]), "+f"(d[2]), "+f"(d[3])
        : "r"(a[0]), "r"(a[1]), "r"(a[2]), "r"(a[3]),
          "r"(b[0]), "r"(b[1]));
}
__device__ __forceinline__ void ldm_x4(unsigned& r0, unsigned& r1,
                                       unsigned& r2, unsigned& r3, uint32_t a) {
    asm volatile("ldmatrix.sync.aligned.m8n8.x4.shared.b16 {%0,%1,%2,%3}, [%4];"
                 : "=r"(r0), "=r"(r1), "=r"(r2), "=r"(r3) : "r"(a));
}

// ---------------------------------------------------------------------------
// weight convert fp32 -> half
// ---------------------------------------------------------------------------
__global__ void h_cvt(const float* __restrict__ s, __half* __restrict__ d, int n)
{
    int i = (blockIdx.x * 256 + threadIdx.x) * 4;
    if (i < n) {
        float4 v = *reinterpret_cast<const float4*>(&s[i]);
        *reinterpret_cast<__half2*>(&d[i])     = __floats2half2_rn(v.x, v.y);
        *reinterpret_cast<__half2*>(&d[i + 2]) = __floats2half2_rn(v.z, v.w);
    }
}

// ---------------------------------------------------------------------------
// LayerNorm: fp32 in, half out
// ---------------------------------------------------------------------------
__global__ void ln_kernel(const float* __restrict__ x,
                          const float* __restrict__ g,
                          const float* __restrict__ b,
                          __half* __restrict__ out)
{
    int row = blockIdx.x;
    long long base = (long long)row * CC;
    int t = threadIdx.x;

    float v[4];
    float s = 0.f, s2 = 0.f;
#pragma unroll
    for (int i = 0; i < 4; i++) {
        v[i] = x[base + t + i * 256];
        s  += v[i];
        s2 += v[i] * v[i];
    }
#pragma unroll
    for (int o = 16; o; o >>= 1) {
        s  += __shfl_xor_sync(0xffffffffu, s, o);
        s2 += __shfl_xor_sync(0xffffffffu, s2, o);
    }
    __shared__ float sh[16];
    int w = t >> 5, l = t & 31;
    if (l == 0) { sh[w] = s; sh[8 + w] = s2; }
    __syncthreads();
    if (t == 0) {
        float a = 0.f, c = 0.f;
#pragma unroll
        for (int i = 0; i < 8; i++) { a += sh[i]; c += sh[8 + i]; }
        sh[0] = a; sh[8] = c;
    }
    __syncthreads();
    float mu  = sh[0] * (1.0f / CC);
    float var = sh[8] * (1.0f / CC) - mu * mu;
    float inv = rsqrtf(var + 1e-5f);
#pragma unroll
    for (int i = 0; i < 4; i++) {
        int c = t + i * 256;
        out[base + c] = __float2half((v[i] - mu) * inv * g[c] + b[c]);
    }
}

// ---------------------------------------------------------------------------
// gemm_h: NT fp16 GEMM, cp.async double-buffer + ldmatrix fragments.
// A [M,K] half, B [Nc,K] half (both K-major). CTA 128x128, BK=32,
// 8 warps (2Mx4N), warp 64x32.
// Epilogue modes: normal (bias/gelu/res, fp32 or half out) or
// expmask (emask != null): out half = mask[c] ? exp2(v*ESCALE) : 0.
// ---------------------------------------------------------------------------
#define ESCALE 0.18033688f   /* 0.125 * log2(e) */

__global__ __launch_bounds__(256, 2)
void gemm_h(const __half* __restrict__ A, const __half* __restrict__ Bm,
            void* __restrict__ Cv,
            int K, int lda, int ldb, int ldc,
            long long Abs, long long Ahs,
            long long Bbs, long long Bhs,
            long long Cbs, long long Chs, int Hh,
            const float* __restrict__ bias,
            const float* __restrict__ res, int act, int outHalf,
            const int* __restrict__ emask)
{
    constexpr int LD = 40;
    constexpr int ROWB = LD * 2;
    constexpr int ASTG_B = 128 * ROWB;
    constexpr int STG_B = 2 * ASTG_B;
    __shared__ __half smh[2 * 256 * LD];

    int zb = blockIdx.z / Hh, zh = blockIdx.z % Hh;
    A  += zb * Abs + zh * Ahs;
    Bm += zb * Bbs + zh * Bhs;

    int t = threadIdx.x, w = t >> 5, lane = t & 31;
    int gid = lane >> 2, tig = lane & 3;
    int m0 = blockIdx.y * 128, n0 = blockIdx.x * 128;
    int wm = (w & 1) * 64, wn = (w >> 1) * 32;

    uint32_t sbase = smem_u32(smh);

    int frow = t >> 1;
    int fch  = (t & 1) * 2;

    auto fill = [&](int p, int k0) {
        uint32_t as = sbase + p * STG_B;
        uint32_t bs = as + ASTG_B;
#pragma unroll
        for (int c = 0; c < 2; c++) {
            int ch = fch + c;
            cp16(as + frow * ROWB + ch * 16,
                 &A[(long long)(m0 + frow) * lda + k0 + ch * 8]);
            cp16(bs + frow * ROWB + ch * 16,
                 &Bm[(long long)(n0 + frow) * ldb + k0 + ch * 8]);
        }
        asm volatile("cp.async.commit_group;" ::: "memory");
    };

    float acc[4][4][4] = {};

    fill(0, 0);
    int S = K / 32;
    for (int s = 0; s < S; s++) {
        int p = s & 1;
        if (s + 1 < S) {
            fill(p ^ 1, (s + 1) * 32);
            asm volatile("cp.async.wait_group 1;" ::: "memory");
        } else {
            asm volatile("cp.async.wait_group 0;" ::: "memory");
        }
        __syncthreads();

        uint32_t as = sbase + p * STG_B;
        uint32_t bs = as + ASTG_B;
#pragma unroll
        for (int kk = 0; kk < 32; kk += 16) {
            unsigned af[4][4], bf[4][2];
            int arow_l = (lane & 15);
            int akoff = kk + ((lane >> 4) << 3);
#pragma unroll
            for (int i = 0; i < 4; i++) {
                uint32_t addr = as + (wm + i * 16 + arow_l) * ROWB + akoff * 2;
                ldm_x4(af[i][0], af[i][1], af[i][2], af[i][3], addr);
            }
            int bj = (lane >> 4) & 1;
            int bkoff = kk + (((lane >> 3) & 1) << 3);
            int brow_l = lane & 7;
#pragma unroll
            for (int jp = 0; jp < 2; jp++) {
                uint32_t addr = bs + (wn + (jp * 2 + bj) * 8 + brow_l) * ROWB + bkoff * 2;
                ldm_x4(bf[jp * 2][0], bf[jp * 2][1],
                       bf[jp * 2 + 1][0], bf[jp * 2 + 1][1], addr);
            }
#pragma unroll
            for (int i = 0; i < 4; i++)
#pragma unroll
                for (int j = 0; j < 4; j++)
                    mma_f16(acc[i][j], af[i], bf[j]);
        }
        __syncthreads();
    }

    // epilogue
    float* Cf = (float*)Cv;
    __half* Ch = (__half*)Cv;
    long long coff = zb * Cbs + zh * Chs;
    const int* mrow = emask ? (emask + (long long)zb * NN_) : nullptr;
#pragma unroll
    for (int i = 0; i < 4; i++) {
        int r1 = m0 + wm + i * 16 + gid;
        int r2 = r1 + 8;
#pragma unroll
        for (int j = 0; j < 4; j++) {
            int c = n0 + wn + j * 8 + 2 * tig;
            float v0 = acc[i][j][0], v1 = acc[i][j][1];
            float v2 = acc[i][j][2], v3 = acc[i][j][3];
            long long i1 = coff + (long long)r1 * ldc + c;
            long long i2 = coff + (long long)r2 * ldc + c;
            if (mrow) {
                bool m0b = mrow[c] != 0, m1b = mrow[c + 1] != 0;
                v0 = m0b ? exp2f(v0 * ESCALE) : 0.f;
                v1 = m1b ? exp2f(v1 * ESCALE) : 0.f;
                v2 = m0b ? exp2f(v2 * ESCALE) : 0.f;
                v3 = m1b ? exp2f(v3 * ESCALE) : 0.f;
                *reinterpret_cast<__half2*>(&Ch[i1]) = __floats2half2_rn(v0, v1);
                *reinterpret_cast<__half2*>(&Ch[i2]) = __floats2half2_rn(v2, v3);
                continue;
            }
            if (bias) {
                float b0 = bias[c], b1 = bias[c + 1];
                v0 += b0; v1 += b1; v2 += b0; v3 += b1;
            }
            if (act) {
                v0 = gelu_exact(v0); v1 = gelu_exact(v1);
                v2 = gelu_exact(v2); v3 = gelu_exact(v3);
            }
            if (res) {
                float2 ra = *reinterpret_cast<const float2*>(&res[(long long)r1 * ldc + c]);
                float2 rb = *reinterpret_cast<const float2*>(&res[(long long)r2 * ldc + c]);
                v0 += ra.x; v1 += ra.y; v2 += rb.x; v3 += rb.y;
            }
            if (outHalf) {
                *reinterpret_cast<__half2*>(&Ch[i1]) = __floats2half2_rn(v0, v1);
                *reinterpret_cast<__half2*>(&Ch[i2]) = __floats2half2_rn(v2, v3);
            } else {
                float2 o1 = {v0, v1}, o2 = {v2, v3};
                *reinterpret_cast<float2*>(&Cf[i1]) = o1;
                *reinterpret_cast<float2*>(&Cf[i2]) = o2;
            }
        }
    }
}

// ---------------------------------------------------------------------------
// norm_kernel: one block per row. Reads unnormalized half u, computes
// S = sum(u), writes fp32 attn = u/S and invS[row]. Deterministic reduction.
// ---------------------------------------------------------------------------
__global__ void norm_kernel(const __half* __restrict__ u,
                            float* __restrict__ attn,
                            float* __restrict__ invS)
{
    long long row = blockIdx.x;
    const __half* ru = u + row * NN_;
    float* ra = attn + row * NN_;
    int t = threadIdx.x;

    // 8 halfs per thread (16B)
    uint4 raw = *reinterpret_cast<const uint4*>(&ru[t * 8]);
    const __half2* h2 = reinterpret_cast<const __half2*>(&raw);
    float v[8];
#pragma unroll
    for (int i = 0; i < 4; i++) {
        float2 f = __half22float2(h2[i]);
        v[2 * i] = f.x; v[2 * i + 1] = f.y;
    }
    float s = 0.f;
#pragma unroll
    for (int i = 0; i < 8; i++) s += v[i];
#pragma unroll
    for (int o = 16; o; o >>= 1)
        s += __shfl_xor_sync(0xffffffffu, s, o);

    __shared__ float sh[8];
    int w = t >> 5, l = t & 31;
    if (l == 0) sh[w] = s;
    __syncthreads();
    float tot = sh[0];
#pragma unroll
    for (int i = 1; i < 8; i++) tot += sh[i];
    float inv = 1.0f / tot;

    float4 o1 = {v[0] * inv, v[1] * inv, v[2] * inv, v[3] * inv};
    float4 o2 = {v[4] * inv, v[5] * inv, v[6] * inv, v[7] * inv};
    *reinterpret_cast<float4*>(&ra[t * 8])     = o1;
    *reinterpret_cast<float4*>(&ra[t * 8 + 4]) = o2;
    if (t == 0) invS[row] = inv;
}

// ---------------------------------------------------------------------------
// gemm_avh: AV fp16 GEMM on UNNORMALIZED u; epilogue scales by invS[row].
// A [N,N] half, V rows=k cols=d half (transposed into smem). CTA 128x64.
// ---------------------------------------------------------------------------
__global__ __launch_bounds__(256, 2)
void gemm_avh(const __half* __restrict__ A, const __half* __restrict__ V,
              __half* __restrict__ C,
              const float* __restrict__ invS,
              int K, int lda, int ldb, int ldc,
              long long Abs, long long Ahs,
              long long Bbs, long long Bhs,
              long long Cbs, long long Chs, int Hh)
{
    constexpr int LD = 40;
    constexpr int ROWB = LD * 2;
    __shared__ __half As[128 * LD];
    __shared__ __half Bs[64 * LD];

    int zb = blockIdx.z / Hh, zh = blockIdx.z % Hh;
    A += zb * Abs + zh * Ahs;
    V += zb * Bbs + zh * Bhs;
    C += zb * Cbs + zh * Chs;
    invS += (long long)(zb * Hh + zh) * NN_;

    int t = threadIdx.x, w = t >> 5, lane = t & 31;
    int gid = lane >> 2, tig = lane & 3;
    int m0 = blockIdx.y * 128;
    int wm = (w & 3) * 32, wn = (w >> 2) * 32;

    int lrow = t >> 2;
    int lcol = (t & 3) * 8;
    int vmr = t >> 3;
    int vdc = (t & 7) * 8;

    uint32_t asb = smem_u32(As);
    uint32_t bsb = smem_u32(Bs);

    float acc[2][4][4] = {};

    for (int k0 = 0; k0 < K; k0 += 32) {
#pragma unroll
        for (int i = 0; i < 2; i++) {
            int r = lrow + 64 * i;
            *reinterpret_cast<uint4*>(&As[r * LD + lcol]) =
                *reinterpret_cast<const uint4*>(&A[(long long)(m0 + r) * lda + k0 + lcol]);
        }
        {
            uint4 u = *reinterpret_cast<const uint4*>(&V[(long long)(k0 + vmr) * ldb + vdc]);
            const __half* hv = reinterpret_cast<const __half*>(&u);
#pragma unroll
            for (int j = 0; j < 8; j++)
                Bs[(vdc + j) * LD + vmr] = hv[j];
        }
        __syncthreads();

#pragma unroll
        for (int kk = 0; kk < 32; kk += 16) {
            unsigned af[2][4], bf[4][2];
            int arow_l = (lane & 15);
            int akoff = kk + ((lane >> 4) << 3);
#pragma unroll
            for (int i = 0; i < 2; i++) {
                uint32_t addr = asb + (wm + i * 16 + arow_l) * ROWB + akoff * 2;
                ldm_x4(af[i][0], af[i][1], af[i][2], af[i][3], addr);
            }
            int bj = (lane >> 4) & 1;
            int bkoff = kk + (((lane >> 3) & 1) << 3);
            int brow_l = lane & 7;
#pragma unroll
            for (int jp = 0; jp < 2; jp++) {
                uint32_t addr = bsb + (wn + (jp * 2 + bj) * 8 + brow_l) * ROWB + bkoff * 2;
                ldm_x4(bf[jp * 2][0], bf[jp * 2][1],
                       bf[jp * 2 + 1][0], bf[jp * 2 + 1][1], addr);
            }
#pragma unroll
            for (int i = 0; i < 2; i++)
#pragma unroll
                for (int j = 0; j < 4; j++)
                    mma_f16(acc[i][j], af[i], bf[j]);
        }
        __syncthreads();
    }

#pragma unroll
    for (int i = 0; i < 2; i++) {
        int r1 = m0 + wm + i * 16 + gid;
        int r2 = r1 + 8;
        float s1 = invS[r1], s2 = invS[r2];
#pragma unroll
        for (int j = 0; j < 4; j++) {
            int c = wn + j * 8 + 2 * tig;
            *reinterpret_cast<__half2*>(&C[(long long)r1 * ldc + c]) =
                __floats2half2_rn(acc[i][j][0] * s1, acc[i][j][1] * s1);
            *reinterpret_cast<__half2*>(&C[(long long)r2 * ldc + c]) =
                __floats2half2_rn(acc[i][j][2] * s2, acc[i][j][3] * s2);
        }
    }
}

// ---------------------------------------------------------------------------
// Launch
// ---------------------------------------------------------------------------
extern "C" void kernel_launch(void* const* d_in, const int* in_sizes, int n_in,
                              void* d_out, int out_size)
{
    const float* x      = (const float*)d_in[0];
    const int*   mask   = (const int*)  d_in[1];
    const float* qkv_w  = (const float*)d_in[2];
    const float* proj_w = (const float*)d_in[3];
    const float* proj_b = (const float*)d_in[4];
    const float* ln1_g  = (const float*)d_in[5];
    const float* ln1_b  = (const float*)d_in[6];
    const float* ln2_g  = (const float*)d_in[7];
    const float* ln2_b  = (const float*)d_in[8];
    const float* fc1_w  = (const float*)d_in[9];
    const float* fc1_b  = (const float*)d_in[10];
    const float* fc2_w  = (const float*)d_in[11];
    const float* fc2_b  = (const float*)d_in[12];

    float* out_x    = (float*)d_out;
    float* out_attn = out_x + (long long)Bb * NN_ * CC;

    __half *p_ln, *p_qkv, *p_ao, *p_h, *p_ph, *p_wq, *p_wp, *p_w1, *p_w2;
    float *p_x1, *p_invs;
    cudaGetSymbolAddress((void**)&p_ln,  g_lnh);
    cudaGetSymbolAddress((void**)&p_qkv, g_qkvh);
    cudaGetSymbolAddress((void**)&p_ao,  g_aoh);
    cudaGetSymbolAddress((void**)&p_x1,  g_x1);
    cudaGetSymbolAddress((void**)&p_h,   g_hbufh);
    cudaGetSymbolAddress((void**)&p_ph,  g_ph);
    cudaGetSymbolAddress((void**)&p_invs, g_invs);
    cudaGetSymbolAddress((void**)&p_wq,  g_wq);
    cudaGetSymbolAddress((void**)&p_wp,  g_wp);
    cudaGetSymbolAddress((void**)&p_w1,  g_w1);
    cudaGetSymbolAddress((void**)&p_w2,  g_w2);

    const int M  = Bb * NN_;                 // 4096
    const long long ZERO = 0;
    const long long NC3 = (long long)NN_ * 3 * CC;

    // 0) weights -> half
    h_cvt<<<3 * CC * CC / 1024, 256>>>(qkv_w,  p_wq, 3 * CC * CC);
    h_cvt<<<CC * CC / 1024,     256>>>(proj_w, p_wp, CC * CC);
    h_cvt<<<DFF_ * CC / 1024,   256>>>(fc1_w,  p_w1, DFF_ * CC);
    h_cvt<<<CC * DFF_ / 1024,   256>>>(fc2_w,  p_w2, CC * DFF_);

    // 1) LN1 -> half
    ln_kernel<<<M, 256>>>(x, ln1_g, ln1_b, p_ln);

    // 2) QKV
    {
        dim3 grid(3 * CC / 128, M / 128, 1);
        gemm_h<<<grid, 256>>>(p_ln, p_wq, p_qkv,
            CC, CC, CC, 3 * CC,
            ZERO, ZERO, ZERO, ZERO, ZERO, ZERO, 1,
            nullptr, nullptr, 0, 1, nullptr);
    }

    // 3) QK^T per head -> g_ph = half(exp(masked scaled logits)), unnormalized
    {
        dim3 grid(NN_ / 128, NN_ / 128, Bb * HH);
        gemm_h<<<grid, 256>>>(p_qkv, p_qkv + CC, p_ph,
            DD, 3 * CC, 3 * CC, NN_,
            NC3, DD, NC3, DD,
            (long long)HH * NN_ * NN_, (long long)NN_ * NN_, HH,
            nullptr, nullptr, 0, 1, mask);
    }

    // 4) normalize: out_attn(fp32) = u/S; invS per row
    norm_kernel<<<Bb * HH * NN_, 256>>>(p_ph, out_attn, p_invs);

    // 5) AV per head on unnormalized u, scaled by invS in epilogue
    {
        dim3 grid(1, NN_ / 128, Bb * HH);
        gemm_avh<<<grid, 256>>>(p_ph, p_qkv + 2 * CC, p_ao, p_invs,
            NN_, NN_, 3 * CC, CC,
            (long long)HH * NN_ * NN_, (long long)NN_ * NN_,
            NC3, DD,
            (long long)NN_ * CC, DD, HH);
    }

    // 6) proj + residual -> x1 (fp32)
    {
        dim3 grid(CC / 128, M / 128, 1);
        gemm_h<<<grid, 256>>>(p_ao, p_wp, p_x1,
            CC, CC, CC, CC,
            ZERO, ZERO, ZERO, ZERO, ZERO, ZERO, 1,
            proj_b, x, 0, 0, nullptr);
    }

    // 7) LN2 -> half
    ln_kernel<<<M, 256>>>(p_x1, ln2_g, ln2_b, p_ln);

    // 8) FC1 + GELU -> half
    {
        dim3 grid(DFF_ / 128, M / 128, 1);
        gemm_h<<<grid, 256>>>(p_ln, p_w1, p_h,
            CC, CC, CC, DFF_,
            ZERO, ZERO, ZERO, ZERO, ZERO, ZERO, 1,
            fc1_b, nullptr, 1, 1, nullptr);
    }

    // 9) FC2 + residual -> out_x (fp32)
    {
        dim3 grid(CC / 128, M / 128, 1);
        gemm_h<<<grid, 256>>>(p_h, p_w2, out_x,
            DFF_, DFF_, DFF_, CC,
            ZERO, ZERO, ZERO, ZERO, ZERO, ZERO, 1,
            fc2_b, p_x1, 0, 0, nullptr);
    }
}